// round 2
// baseline (speedup 1.0000x reference)
#include <cuda_runtime.h>

// DANet spatial attention, fp32 baseline.
// B=16, C=512, H=W=48 -> HW=2304, d=64.
//
// Pipeline:
//   1. proj_kernel x3:  Q,K: [B,64,HW], V: [B,512,HW]   (P = W @ X + bias)
//   2. scores_kernel:   S[b,n,m] = sum_d Q[b,d,n]*K[b,d,m]
//   3. softmax_kernel:  row-wise softmax over m (2304)
//   4. out_kernel:      Y[b,c,n] = gamma * sum_m V[b,c,m]*A[b,n,m] + X[b,c,n]

#define NB 16
#define NC 512
#define NHW 2304
#define ND 64

// Scratch (allocation-free rule: __device__ globals)
__device__ float g_Q[(size_t)NB * ND * NHW];               //  9.4 MB
__device__ float g_K[(size_t)NB * ND * NHW];               //  9.4 MB
__device__ float g_V[(size_t)NB * NC * NHW];               // 75.5 MB
__device__ float g_A[(size_t)NB * NHW * NHW];              //  340 MB

// ---------------------------------------------------------------------------
// P[b][o][n] = sum_c W[o][c] * X[b][c][n] + bias[o]
// grid: (HW/64, O/64, B), block: 256, tile 64(o) x 64(n), k-chunk 16(c)
// ---------------------------------------------------------------------------
__global__ void proj_kernel(const float* __restrict__ X, const float* __restrict__ W,
                            const float* __restrict__ bias, float* __restrict__ P,
                            int O) {
    const int b  = blockIdx.z;
    const int n0 = blockIdx.x * 64;
    const int o0 = blockIdx.y * 64;
    const float* Xb = X + (size_t)b * NC * NHW;
    float*       Pb = P + (size_t)b * O * NHW;

    __shared__ float Ws[16][65];   // [c][o]  (transposed for contiguous a-reg loads)
    __shared__ float Xs[16][65];   // [c][n]

    const int tid = threadIdx.x;
    const int tx = tid & 15, ty = tid >> 4;   // 16x16 thread tile, 4x4 per thread
    float acc[4][4] = {};

    for (int c0 = 0; c0 < NC; c0 += 16) {
        {   // W tile: 64 o x 16 c (gmem row-major [O][C])
            int c = tid & 15;
            int o = tid >> 4;               // 16 o per pass
            #pragma unroll
            for (int p = 0; p < 4; p++)
                Ws[c][o + p * 16] = W[(size_t)(o0 + o + p * 16) * NC + c0 + c];
        }
        {   // X tile: 16 c x 64 n (n contiguous -> coalesced)
            int n = tid & 63;
            int c = tid >> 6;               // 4 c per pass
            #pragma unroll
            for (int p = 0; p < 4; p++)
                Xs[c + p * 4][n] = Xb[(size_t)(c0 + c + p * 4) * NHW + n0 + n];
        }
        __syncthreads();
        #pragma unroll
        for (int c = 0; c < 16; c++) {
            float a[4], bb[4];
            #pragma unroll
            for (int i = 0; i < 4; i++) a[i]  = Ws[c][ty * 4 + i];
            #pragma unroll
            for (int j = 0; j < 4; j++) bb[j] = Xs[c][tx * 4 + j];
            #pragma unroll
            for (int i = 0; i < 4; i++)
                #pragma unroll
                for (int j = 0; j < 4; j++)
                    acc[i][j] = fmaf(a[i], bb[j], acc[i][j]);
        }
        __syncthreads();
    }
    #pragma unroll
    for (int i = 0; i < 4; i++) {
        int o = o0 + ty * 4 + i;
        float bo = bias[o];
        #pragma unroll
        for (int j = 0; j < 4; j++)
            Pb[(size_t)o * NHW + n0 + tx * 4 + j] = acc[i][j] + bo;
    }
}

// ---------------------------------------------------------------------------
// S[b][n][m] = sum_d Q[b][d][n] * K[b][d][m]     (K-dim = 64, single pass)
// grid: (HW/64 m-tiles, HW/64 n-tiles, B), block 256, tile 64x64
// ---------------------------------------------------------------------------
__global__ void scores_kernel(const float* __restrict__ Q, const float* __restrict__ K,
                              float* __restrict__ S) {
    const int b  = blockIdx.z;
    const int m0 = blockIdx.x * 64;
    const int n0 = blockIdx.y * 64;
    const float* Qb = Q + (size_t)b * ND * NHW;
    const float* Kb = K + (size_t)b * ND * NHW;
    float*       Sb = S + (size_t)b * NHW * NHW;

    __shared__ float Qs[64][65];   // [d][n]
    __shared__ float Ks[64][65];   // [d][m]

    const int tid = threadIdx.x;
    const int tx = tid & 15, ty = tid >> 4;

    {   // load: both tiles 64 d x 64 cols, cols contiguous in gmem
        int x = tid & 63, r = tid >> 6;     // 4 d-rows per pass
        #pragma unroll
        for (int p = 0; p < 16; p++) {
            int d = r + p * 4;
            Qs[d][x] = Qb[(size_t)d * NHW + n0 + x];
            Ks[d][x] = Kb[(size_t)d * NHW + m0 + x];
        }
    }
    __syncthreads();

    float acc[4][4] = {};
    #pragma unroll 8
    for (int d = 0; d < ND; d++) {
        float a[4], bb[4];
        #pragma unroll
        for (int i = 0; i < 4; i++) a[i]  = Qs[d][ty * 4 + i];
        #pragma unroll
        for (int j = 0; j < 4; j++) bb[j] = Ks[d][tx * 4 + j];
        #pragma unroll
        for (int i = 0; i < 4; i++)
            #pragma unroll
            for (int j = 0; j < 4; j++)
                acc[i][j] = fmaf(a[i], bb[j], acc[i][j]);
    }

    #pragma unroll
    for (int i = 0; i < 4; i++)
        #pragma unroll
        for (int j = 0; j < 4; j++)
            Sb[(size_t)(n0 + ty * 4 + i) * NHW + m0 + tx * 4 + j] = acc[i][j];
}

// ---------------------------------------------------------------------------
// Row softmax over m=2304. One block (256 threads) per row; 9 elems/thread in regs.
// grid: B*HW, block 256
// ---------------------------------------------------------------------------
__global__ void softmax_kernel(float* __restrict__ A) {
    float* p = A + (size_t)blockIdx.x * NHW;
    const int tid = threadIdx.x;

    float r[9];
    float mx = -1e30f;
    #pragma unroll
    for (int i = 0; i < 9; i++) {
        r[i] = p[tid + i * 256];
        mx = fmaxf(mx, r[i]);
    }

    __shared__ float red[8];
    #pragma unroll
    for (int off = 16; off > 0; off >>= 1)
        mx = fmaxf(mx, __shfl_xor_sync(0xffffffffu, mx, off));
    if ((tid & 31) == 0) red[tid >> 5] = mx;
    __syncthreads();
    float bm = red[0];
    #pragma unroll
    for (int w = 1; w < 8; w++) bm = fmaxf(bm, red[w]);
    __syncthreads();

    float s = 0.f;
    #pragma unroll
    for (int i = 0; i < 9; i++) {
        r[i] = __expf(r[i] - bm);
        s += r[i];
    }
    #pragma unroll
    for (int off = 16; off > 0; off >>= 1)
        s += __shfl_xor_sync(0xffffffffu, s, off);
    if ((tid & 31) == 0) red[tid >> 5] = s;
    __syncthreads();
    float bs = 0.f;
    #pragma unroll
    for (int w = 0; w < 8; w++) bs += red[w];

    float inv = 1.f / bs;
    #pragma unroll
    for (int i = 0; i < 9; i++)
        p[tid + i * 256] = r[i] * inv;
}

// ---------------------------------------------------------------------------
// Y[b][c][n] = gamma * sum_m V[b][c][m] * A[b][n][m]  +  X[b][c][n]
// grid: (HW/64 n-tiles, C/64 c-tiles, B), block 256, k-chunk 32(m)
// ---------------------------------------------------------------------------
__global__ void out_kernel(const float* __restrict__ V, const float* __restrict__ A,
                           const float* __restrict__ X, const float* __restrict__ gamma,
                           float* __restrict__ Y) {
    const int b  = blockIdx.z;
    const int n0 = blockIdx.x * 64;
    const int c0 = blockIdx.y * 64;
    const float* Vb = V + (size_t)b * NC * NHW;
    const float* Ab = A + (size_t)b * NHW * NHW;
    const float* Xb = X + (size_t)b * NC * NHW;
    float*       Yb = Y + (size_t)b * NC * NHW;

    __shared__ float Vs[64][33];   // [c][m], +1 pad to break bank conflicts
    __shared__ float As[64][33];   // [n][m]

    const int tid = threadIdx.x;
    const int tx = tid & 15, ty = tid >> 4;
    float acc[4][4] = {};

    for (int m0 = 0; m0 < NHW; m0 += 32) {
        {   // both tiles: 64 rows x 32 m, m contiguous -> coalesced 128B
            int m = tid & 31, r = tid >> 5;   // 8 rows per pass
            #pragma unroll
            for (int p = 0; p < 8; p++) {
                Vs[r + p * 8][m] = Vb[(size_t)(c0 + r + p * 8) * NHW + m0 + m];
                As[r + p * 8][m] = Ab[(size_t)(n0 + r + p * 8) * NHW + m0 + m];
            }
        }
        __syncthreads();
        #pragma unroll
        for (int m = 0; m < 32; m++) {
            float a[4], bb[4];
            #pragma unroll
            for (int i = 0; i < 4; i++) a[i]  = Vs[ty * 4 + i][m];
            #pragma unroll
            for (int j = 0; j < 4; j++) bb[j] = As[tx * 4 + j][m];
            #pragma unroll
            for (int i = 0; i < 4; i++)
                #pragma unroll
                for (int j = 0; j < 4; j++)
                    acc[i][j] = fmaf(a[i], bb[j], acc[i][j]);
        }
        __syncthreads();
    }

    const float g = gamma[0];
    #pragma unroll
    for (int i = 0; i < 4; i++) {
        int c = c0 + ty * 4 + i;
        #pragma unroll
        for (int j = 0; j < 4; j++) {
            int n = n0 + tx * 4 + j;
            size_t idx = (size_t)c * NHW + n;
            Yb[idx] = g * acc[i][j] + Xb[idx];
        }
    }
}

// ---------------------------------------------------------------------------
extern "C" void kernel_launch(void* const* d_in, const int* in_sizes, int n_in,
                              void* d_out, int out_size) {
    const float* X     = (const float*)d_in[0];
    const float* Wq    = (const float*)d_in[1];
    const float* bq    = (const float*)d_in[2];
    const float* Wk    = (const float*)d_in[3];
    const float* bk    = (const float*)d_in[4];
    const float* Wv    = (const float*)d_in[5];
    const float* bv    = (const float*)d_in[6];
    const float* gamma = (const float*)d_in[7];
    float* Y = (float*)d_out;

    float *Q, *K, *V, *A;
    cudaGetSymbolAddress((void**)&Q, g_Q);
    cudaGetSymbolAddress((void**)&K, g_K);
    cudaGetSymbolAddress((void**)&V, g_V);
    cudaGetSymbolAddress((void**)&A, g_A);

    dim3 blk(256);
    proj_kernel<<<dim3(NHW / 64, ND / 64, NB), blk>>>(X, Wq, bq, Q, ND);
    proj_kernel<<<dim3(NHW / 64, ND / 64, NB), blk>>>(X, Wk, bk, K, ND);
    proj_kernel<<<dim3(NHW / 64, NC / 64, NB), blk>>>(X, Wv, bv, V, NC);
    scores_kernel<<<dim3(NHW / 64, NHW / 64, NB), blk>>>(Q, K, A);
    softmax_kernel<<<NB * NHW, 256>>>(A);
    out_kernel<<<dim3(NHW / 64, NC / 64, NB), blk>>>(V, A, X, gamma, Y);
}

// round 3
// speedup vs baseline: 1.3354x; 1.3354x over previous
#include <cuda_runtime.h>

// DANet spatial attention, fp32, 128x128 SIMT GEMM tiles (8x8 per thread).
// B=16, C=512, H=W=48 -> HW=2304, d=64.

#define NB 16
#define NC 512
#define NHW 2304
#define ND 64

__device__ float g_Q[(size_t)NB * ND * NHW];
__device__ float g_K[(size_t)NB * ND * NHW];
__device__ float g_V[(size_t)NB * NC * NHW];
__device__ float g_A[(size_t)NB * NHW * NHW];

// ---------------------------------------------------------------------------
// Small projection (Q, K: O=64). 64x64 tile, 4x4 per thread. (minor cost)
// ---------------------------------------------------------------------------
__global__ void proj_kernel(const float* __restrict__ X, const float* __restrict__ W,
                            const float* __restrict__ bias, float* __restrict__ P,
                            int O) {
    const int b  = blockIdx.z;
    const int n0 = blockIdx.x * 64;
    const int o0 = blockIdx.y * 64;
    const float* Xb = X + (size_t)b * NC * NHW;
    float*       Pb = P + (size_t)b * O * NHW;

    __shared__ float Ws[16][65];
    __shared__ float Xs[16][65];

    const int tid = threadIdx.x;
    const int tx = tid & 15, ty = tid >> 4;
    float acc[4][4] = {};

    for (int c0 = 0; c0 < NC; c0 += 16) {
        {
            int c = tid & 15;
            int o = tid >> 4;
            #pragma unroll
            for (int p = 0; p < 4; p++)
                Ws[c][o + p * 16] = W[(size_t)(o0 + o + p * 16) * NC + c0 + c];
        }
        {
            int n = tid & 63;
            int c = tid >> 6;
            #pragma unroll
            for (int p = 0; p < 4; p++)
                Xs[c + p * 4][n] = Xb[(size_t)(c0 + c + p * 4) * NHW + n0 + n];
        }
        __syncthreads();
        #pragma unroll
        for (int c = 0; c < 16; c++) {
            float a[4], bb[4];
            #pragma unroll
            for (int i = 0; i < 4; i++) a[i]  = Ws[c][ty * 4 + i];
            #pragma unroll
            for (int j = 0; j < 4; j++) bb[j] = Xs[c][tx * 4 + j];
            #pragma unroll
            for (int i = 0; i < 4; i++)
                #pragma unroll
                for (int j = 0; j < 4; j++)
                    acc[i][j] = fmaf(a[i], bb[j], acc[i][j]);
        }
        __syncthreads();
    }
    #pragma unroll
    for (int i = 0; i < 4; i++) {
        int o = o0 + ty * 4 + i;
        float bo = bias[o];
        #pragma unroll
        for (int j = 0; j < 4; j++)
            Pb[(size_t)o * NHW + n0 + tx * 4 + j] = acc[i][j] + bo;
    }
}

// ---------------------------------------------------------------------------
// V projection: P[b][o][n] = sum_c W[o][c]*X[b][c][n] + bias[o]
// 128(o) x 128(n), k-chunk 16(c), 8x8 per thread, reg-prefetch pipeline.
// ---------------------------------------------------------------------------
__global__ void __launch_bounds__(256, 2)
proj_big_kernel(const float* __restrict__ X, const float* __restrict__ W,
                const float* __restrict__ bias, float* __restrict__ P) {
    const int b  = blockIdx.z;
    const int n0 = blockIdx.x * 128;
    const int o0 = blockIdx.y * 128;
    const float* Xb = X + (size_t)b * NC * NHW;
    float*       Pb = P + (size_t)b * NC * NHW;

    __shared__ float Ws[16][132];   // [c][o]   (transposed on store)
    __shared__ float Xs[16][132];   // [c][n]

    const int tid = threadIdx.x;
    const int tx = tid & 15, ty = tid >> 4;

    // W loader: 128 o-rows x 16 c; each thread 2 float4 along c, store transposed
    const int wr = tid >> 2, wc4 = tid & 3;
    // X loader: 16 c-rows x 128 n; each thread 2 float4 along n, store direct
    const int xr = tid >> 5, xc4 = tid & 31;

    float4 rw[2], rx[2];
    float acc[8][8] = {};

    #pragma unroll 1
    for (int c0 = 0; c0 < NC; c0 += 16) {
        // load chunk (prefetched into regs at bottom of previous iter for c0>0)
        if (c0 == 0) {
            #pragma unroll
            for (int p = 0; p < 2; p++) {
                rw[p] = *(const float4*)&W [(size_t)(o0 + wr + p * 64) * NC  + c0 + wc4 * 4];
                rx[p] = *(const float4*)&Xb[(size_t)(c0 + xr + p * 8 ) * NHW + n0 + xc4 * 4];
            }
        }
        // store to smem
        #pragma unroll
        for (int p = 0; p < 2; p++) {
            int row = wr + p * 64;
            Ws[wc4 * 4 + 0][row] = rw[p].x;
            Ws[wc4 * 4 + 1][row] = rw[p].y;
            Ws[wc4 * 4 + 2][row] = rw[p].z;
            Ws[wc4 * 4 + 3][row] = rw[p].w;
            *(float4*)&Xs[xr + p * 8][xc4 * 4] = rx[p];
        }
        __syncthreads();
        if (c0 + 16 < NC) {
            #pragma unroll
            for (int p = 0; p < 2; p++) {
                rw[p] = *(const float4*)&W [(size_t)(o0 + wr + p * 64) * NC  + c0 + 16 + wc4 * 4];
                rx[p] = *(const float4*)&Xb[(size_t)(c0 + 16 + xr + p * 8) * NHW + n0 + xc4 * 4];
            }
        }
        #pragma unroll
        for (int c = 0; c < 16; c++) {
            float4 a0 = *(const float4*)&Ws[c][ty * 8];
            float4 a1 = *(const float4*)&Ws[c][ty * 8 + 4];
            float4 b0 = *(const float4*)&Xs[c][tx * 8];
            float4 b1 = *(const float4*)&Xs[c][tx * 8 + 4];
            float a[8] = {a0.x,a0.y,a0.z,a0.w,a1.x,a1.y,a1.z,a1.w};
            float bb[8] = {b0.x,b0.y,b0.z,b0.w,b1.x,b1.y,b1.z,b1.w};
            #pragma unroll
            for (int i = 0; i < 8; i++)
                #pragma unroll
                for (int j = 0; j < 8; j++)
                    acc[i][j] = fmaf(a[i], bb[j], acc[i][j]);
        }
        __syncthreads();
    }

    #pragma unroll
    for (int i = 0; i < 8; i++) {
        int o = o0 + ty * 8 + i;
        float bo = bias[o];
        #pragma unroll
        for (int jj = 0; jj < 2; jj++) {
            float4 y;
            y.x = acc[i][jj*4+0] + bo;
            y.y = acc[i][jj*4+1] + bo;
            y.z = acc[i][jj*4+2] + bo;
            y.w = acc[i][jj*4+3] + bo;
            *(float4*)&Pb[(size_t)o * NHW + n0 + tx * 8 + jj * 4] = y;
        }
    }
}

// ---------------------------------------------------------------------------
// S[b][n][m] = sum_d Q[b][d][n]*K[b][d][m].  128(n) x 128(m), K=64 (2x32 chunks)
// ---------------------------------------------------------------------------
__global__ void __launch_bounds__(256, 2)
scores_kernel(const float* __restrict__ Q, const float* __restrict__ K,
              float* __restrict__ S) {
    const int b  = blockIdx.z;
    const int m0 = blockIdx.x * 128;
    const int n0 = blockIdx.y * 128;
    const float* Qb = Q + (size_t)b * ND * NHW;
    const float* Kb = K + (size_t)b * ND * NHW;
    float*       Sb = S + (size_t)b * NHW * NHW;

    __shared__ float Qs[32][128];   // [d][n]
    __shared__ float Ks[32][128];   // [d][m]

    const int tid = threadIdx.x;
    const int tx = tid & 15, ty = tid >> 4;
    const int lr = tid >> 5, lc4 = tid & 31;   // 4 passes: rows 0..31

    float4 rq[4], rk[4];
    float acc[8][8] = {};

    #pragma unroll 1
    for (int d0 = 0; d0 < ND; d0 += 32) {
        if (d0 == 0) {
            #pragma unroll
            for (int p = 0; p < 4; p++) {
                rq[p] = *(const float4*)&Qb[(size_t)(d0 + lr + p * 8) * NHW + n0 + lc4 * 4];
                rk[p] = *(const float4*)&Kb[(size_t)(d0 + lr + p * 8) * NHW + m0 + lc4 * 4];
            }
        }
        #pragma unroll
        for (int p = 0; p < 4; p++) {
            *(float4*)&Qs[lr + p * 8][lc4 * 4] = rq[p];
            *(float4*)&Ks[lr + p * 8][lc4 * 4] = rk[p];
        }
        __syncthreads();
        if (d0 + 32 < ND) {
            #pragma unroll
            for (int p = 0; p < 4; p++) {
                rq[p] = *(const float4*)&Qb[(size_t)(d0 + 32 + lr + p * 8) * NHW + n0 + lc4 * 4];
                rk[p] = *(const float4*)&Kb[(size_t)(d0 + 32 + lr + p * 8) * NHW + m0 + lc4 * 4];
            }
        }
        #pragma unroll
        for (int d = 0; d < 32; d++) {
            float4 a0 = *(const float4*)&Qs[d][ty * 8];
            float4 a1 = *(const float4*)&Qs[d][ty * 8 + 4];
            float4 b0 = *(const float4*)&Ks[d][tx * 8];
            float4 b1 = *(const float4*)&Ks[d][tx * 8 + 4];
            float a[8] = {a0.x,a0.y,a0.z,a0.w,a1.x,a1.y,a1.z,a1.w};
            float bb[8] = {b0.x,b0.y,b0.z,b0.w,b1.x,b1.y,b1.z,b1.w};
            #pragma unroll
            for (int i = 0; i < 8; i++)
                #pragma unroll
                for (int j = 0; j < 8; j++)
                    acc[i][j] = fmaf(a[i], bb[j], acc[i][j]);
        }
        __syncthreads();
    }

    #pragma unroll
    for (int i = 0; i < 8; i++) {
        size_t rowoff = (size_t)(n0 + ty * 8 + i) * NHW + m0;
        #pragma unroll
        for (int jj = 0; jj < 2; jj++) {
            float4 y;
            y.x = acc[i][jj*4+0]; y.y = acc[i][jj*4+1];
            y.z = acc[i][jj*4+2]; y.w = acc[i][jj*4+3];
            *(float4*)&Sb[rowoff + tx * 8 + jj * 4] = y;
        }
    }
}

// ---------------------------------------------------------------------------
// Row softmax over m=2304. One block (256 threads) per row.
// ---------------------------------------------------------------------------
__global__ void softmax_kernel(float* __restrict__ A) {
    float* p = A + (size_t)blockIdx.x * NHW;
    const int tid = threadIdx.x;

    float r[9];
    float mx = -1e30f;
    #pragma unroll
    for (int i = 0; i < 9; i++) {
        r[i] = p[tid + i * 256];
        mx = fmaxf(mx, r[i]);
    }

    __shared__ float red[8];
    #pragma unroll
    for (int off = 16; off > 0; off >>= 1)
        mx = fmaxf(mx, __shfl_xor_sync(0xffffffffu, mx, off));
    if ((tid & 31) == 0) red[tid >> 5] = mx;
    __syncthreads();
    float bm = red[0];
    #pragma unroll
    for (int w = 1; w < 8; w++) bm = fmaxf(bm, red[w]);
    __syncthreads();

    float s = 0.f;
    #pragma unroll
    for (int i = 0; i < 9; i++) {
        r[i] = __expf(r[i] - bm);
        s += r[i];
    }
    #pragma unroll
    for (int off = 16; off > 0; off >>= 1)
        s += __shfl_xor_sync(0xffffffffu, s, off);
    if ((tid & 31) == 0) red[tid >> 5] = s;
    __syncthreads();
    float bs = 0.f;
    #pragma unroll
    for (int w = 0; w < 8; w++) bs += red[w];

    float inv = 1.f / bs;
    #pragma unroll
    for (int i = 0; i < 9; i++)
        p[tid + i * 256] = r[i] * inv;
}

// ---------------------------------------------------------------------------
// Y[b][c][n] = gamma * sum_m V[b][c][m]*A[b][n][m] + X[b][c][n]
// 128(c) x 128(n), k-chunk 16(m), 8x8 per thread, transpose-on-store smem.
// ---------------------------------------------------------------------------
__global__ void __launch_bounds__(256, 2)
out_kernel(const float* __restrict__ V, const float* __restrict__ A,
           const float* __restrict__ X, const float* __restrict__ gamma,
           float* __restrict__ Y) {
    const int b  = blockIdx.z;
    const int n0 = blockIdx.x * 128;
    const int c0 = blockIdx.y * 128;
    const float* Vb = V + (size_t)b * NC * NHW;
    const float* Ab = A + (size_t)b * NHW * NHW;
    const float* Xb = X + (size_t)b * NC * NHW;
    float*       Yb = Y + (size_t)b * NC * NHW;

    __shared__ float Vs[16][132];   // [m][c]
    __shared__ float As[16][132];   // [m][n]

    const int tid = threadIdx.x;
    const int tx = tid & 15, ty = tid >> 4;
    const int r0 = tid >> 2, c4 = tid & 3;   // 128 rows x 4 float4; 2 per thread

    float4 rv[2], ra[2];
    float acc[8][8] = {};

    #pragma unroll 1
    for (int m0 = 0; m0 < NHW; m0 += 16) {
        if (m0 == 0) {
            #pragma unroll
            for (int p = 0; p < 2; p++) {
                int row = r0 + p * 64;
                rv[p] = *(const float4*)&Vb[(size_t)(c0 + row) * NHW + m0 + c4 * 4];
                ra[p] = *(const float4*)&Ab[(size_t)(n0 + row) * NHW + m0 + c4 * 4];
            }
        }
        #pragma unroll
        for (int p = 0; p < 2; p++) {
            int row = r0 + p * 64;
            Vs[c4 * 4 + 0][row] = rv[p].x;
            Vs[c4 * 4 + 1][row] = rv[p].y;
            Vs[c4 * 4 + 2][row] = rv[p].z;
            Vs[c4 * 4 + 3][row] = rv[p].w;
            As[c4 * 4 + 0][row] = ra[p].x;
            As[c4 * 4 + 1][row] = ra[p].y;
            As[c4 * 4 + 2][row] = ra[p].z;
            As[c4 * 4 + 3][row] = ra[p].w;
        }
        __syncthreads();
        if (m0 + 16 < NHW) {
            #pragma unroll
            for (int p = 0; p < 2; p++) {
                int row = r0 + p * 64;
                rv[p] = *(const float4*)&Vb[(size_t)(c0 + row) * NHW + m0 + 16 + c4 * 4];
                ra[p] = *(const float4*)&Ab[(size_t)(n0 + row) * NHW + m0 + 16 + c4 * 4];
            }
        }
        #pragma unroll
        for (int m = 0; m < 16; m++) {
            float4 a0 = *(const float4*)&Vs[m][ty * 8];
            float4 a1 = *(const float4*)&Vs[m][ty * 8 + 4];
            float4 b0 = *(const float4*)&As[m][tx * 8];
            float4 b1 = *(const float4*)&As[m][tx * 8 + 4];
            float a[8] = {a0.x,a0.y,a0.z,a0.w,a1.x,a1.y,a1.z,a1.w};
            float bb[8] = {b0.x,b0.y,b0.z,b0.w,b1.x,b1.y,b1.z,b1.w};
            #pragma unroll
            for (int i = 0; i < 8; i++)
                #pragma unroll
                for (int j = 0; j < 8; j++)
                    acc[i][j] = fmaf(a[i], bb[j], acc[i][j]);
        }
        __syncthreads();
    }

    const float g = gamma[0];
    #pragma unroll
    for (int i = 0; i < 8; i++) {
        int c = c0 + ty * 8 + i;
        size_t rowoff = (size_t)c * NHW + n0;
        #pragma unroll
        for (int jj = 0; jj < 2; jj++) {
            size_t idx = rowoff + tx * 8 + jj * 4;
            float4 x4 = *(const float4*)&Xb[idx];
            float4 y;
            y.x = g * acc[i][jj*4+0] + x4.x;
            y.y = g * acc[i][jj*4+1] + x4.y;
            y.z = g * acc[i][jj*4+2] + x4.z;
            y.w = g * acc[i][jj*4+3] + x4.w;
            *(float4*)&Yb[idx] = y;
        }
    }
}

// ---------------------------------------------------------------------------
extern "C" void kernel_launch(void* const* d_in, const int* in_sizes, int n_in,
                              void* d_out, int out_size) {
    const float* X     = (const float*)d_in[0];
    const float* Wq    = (const float*)d_in[1];
    const float* bq    = (const float*)d_in[2];
    const float* Wk    = (const float*)d_in[3];
    const float* bk    = (const float*)d_in[4];
    const float* Wv    = (const float*)d_in[5];
    const float* bv    = (const float*)d_in[6];
    const float* gamma = (const float*)d_in[7];
    float* Y = (float*)d_out;

    float *Q, *K, *V, *A;
    cudaGetSymbolAddress((void**)&Q, g_Q);
    cudaGetSymbolAddress((void**)&K, g_K);
    cudaGetSymbolAddress((void**)&V, g_V);
    cudaGetSymbolAddress((void**)&A, g_A);

    dim3 blk(256);
    proj_kernel<<<dim3(NHW / 64, ND / 64, NB), blk>>>(X, Wq, bq, Q, ND);
    proj_kernel<<<dim3(NHW / 64, ND / 64, NB), blk>>>(X, Wk, bk, K, ND);
    proj_big_kernel<<<dim3(NHW / 128, NC / 128, NB), blk>>>(X, Wv, bv, V);
    scores_kernel<<<dim3(NHW / 128, NHW / 128, NB), blk>>>(Q, K, A);
    softmax_kernel<<<NB * NHW, 256>>>(A);
    out_kernel<<<dim3(NHW / 128, NC / 128, NB), blk>>>(V, A, X, gamma, Y);
}

// round 4
// speedup vs baseline: 3.9853x; 2.9843x over previous
#include <cuda_runtime.h>
#include <cstdint>

// DANet spatial attention — TF32 tensor-core GEMMs (mma.sync.m16n8k8).
// B=16, C=512, HW=2304, d=64.

#define NB 16
#define NC 512
#define NHW 2304
#define ND 64

__device__ float g_QK[(size_t)NB * 128 * NHW];   // rows 0..63 = Q, 64..127 = K
__device__ float g_V [(size_t)NB * NC  * NHW];
__device__ float g_A [(size_t)NB * NHW * NHW];

// ---------------------------------------------------------------------------
__device__ __forceinline__ unsigned cvt_tf32(float x) {
    unsigned u; asm("cvt.rna.tf32.f32 %0, %1;" : "=r"(u) : "f"(x)); return u;
}
__device__ __forceinline__ float round_tf32(float x) {
    return __uint_as_float(cvt_tf32(x));
}
__device__ __forceinline__ void mma_tf32(float c[4],
                                         unsigned a0, unsigned a1, unsigned a2, unsigned a3,
                                         unsigned b0, unsigned b1) {
    asm volatile(
        "mma.sync.aligned.m16n8k8.row.col.f32.tf32.tf32.f32 "
        "{%0,%1,%2,%3}, {%4,%5,%6,%7}, {%8,%9}, {%0,%1,%2,%3};"
        : "+f"(c[0]), "+f"(c[1]), "+f"(c[2]), "+f"(c[3])
        : "r"(a0), "r"(a1), "r"(a2), "r"(a3), "r"(b0), "r"(b1));
}
#define CPA16(dst, src) asm volatile("cp.async.ca.shared.global [%0], [%1], 16;\n" :: "r"(dst), "l"(src))
#define CP_COMMIT()     asm volatile("cp.async.commit_group;\n")
#define CP_WAIT1()      asm volatile("cp.async.wait_group 1;\n")

// Strides (in floats): RK tiles [128 rows][16 k] pad->20 ; KN tiles [16 k][128 cols] pad->136
#define SRK 20
#define SKN 136

// ---------------------------------------------------------------------------
// Projection: P[o][n] = round_tf32( sum_c W[o][c] * X[c][n] + bias[o] )
// A = W (RK layout), B = X (KN layout). cvt applied on fragments (raw inputs).
// grid: (NHW/128, O/128, NB), block 128.
// ---------------------------------------------------------------------------
__global__ void __launch_bounds__(128)
proj_tf32(const float* __restrict__ X,
          const float* __restrict__ W1, const float* __restrict__ B1,
          const float* __restrict__ W2, const float* __restrict__ B2,
          int split, float* __restrict__ P) {
    const int b  = blockIdx.z;
    const int n0 = blockIdx.x * 128;
    const int o0 = blockIdx.y * 128;
    const int O  = gridDim.y * 128;
    const float* Xb = X + (size_t)b * NC * NHW;
    float*       Pb = P + (size_t)b * O * NHW;

    __shared__ float sA[2][128 * SRK];
    __shared__ float sB[2][16 * SKN];

    const int tid = threadIdx.x;
    const int lane = tid & 31, wid = tid >> 5;
    const int wm = (wid >> 1) * 64, wn = (wid & 1) * 64;
    const int lr = lane >> 2, lc = lane & 3;

    // loader maps: A: 512 float4 (row=idx>>2, c4=idx&3); B: 512 float4 (k=idx>>5, n4=idx&31)
    const int arow0 = tid >> 2, ac4 = tid & 3;
    const int brow0 = tid >> 5, bn4 = tid & 31;
    const float* Arows[4];
    #pragma unroll
    for (int p = 0; p < 4; p++) {
        int row = o0 + arow0 + p * 32;
        Arows[p] = (row < split ? W1 + (size_t)row * NC
                                : W2 + (size_t)(row - split) * NC);
    }
    const unsigned sAu = (unsigned)__cvta_generic_to_shared(&sA[0][0]);
    const unsigned sBu = (unsigned)__cvta_generic_to_shared(&sB[0][0]);

    float acc[4][8][4];
    #pragma unroll
    for (int i = 0; i < 4; i++)
        #pragma unroll
        for (int j = 0; j < 8; j++)
            #pragma unroll
            for (int q = 0; q < 4; q++) acc[i][j][q] = 0.f;

    const int NCH = NC / 16;
    #define PROJ_LOAD(ch, buf) {                                                      \
        int c0 = (ch) * 16;                                                           \
        _Pragma("unroll")                                                             \
        for (int p = 0; p < 4; p++) {                                                 \
            int row = arow0 + p * 32;                                                 \
            CPA16(sAu + ((buf) * 128 * SRK + row * SRK + ac4 * 4) * 4,                \
                  Arows[p] + c0 + ac4 * 4);                                           \
            int kr = brow0 + p * 4;                                                   \
            CPA16(sBu + ((buf) * 16 * SKN + kr * SKN + bn4 * 4) * 4,                  \
                  Xb + (size_t)(c0 + kr) * NHW + n0 + bn4 * 4);                       \
        }                                                                             \
    }

    PROJ_LOAD(0, 0); CP_COMMIT();
    for (int ch = 0; ch < NCH; ch++) {
        int buf = ch & 1;
        if (ch + 1 < NCH) { PROJ_LOAD(ch + 1, buf ^ 1); }
        CP_COMMIT();
        CP_WAIT1();
        __syncthreads();
        const float* As = sA[buf];
        const float* Bs = sB[buf];
        #pragma unroll
        for (int ks = 0; ks < 2; ks++) {
            const int kb = ks * 8;
            unsigned a[4][4];
            #pragma unroll
            for (int i = 0; i < 4; i++) {
                const float* ap = As + (wm + i * 16 + lr) * SRK + kb + lc;
                a[i][0] = cvt_tf32(ap[0]);
                a[i][1] = cvt_tf32(ap[8 * SRK]);
                a[i][2] = cvt_tf32(ap[4]);
                a[i][3] = cvt_tf32(ap[8 * SRK + 4]);
            }
            unsigned bb[8][2];
            #pragma unroll
            for (int j = 0; j < 8; j++) {
                const float* bp = Bs + (kb + lc) * SKN + wn + j * 8 + lr;
                bb[j][0] = cvt_tf32(bp[0]);
                bb[j][1] = cvt_tf32(bp[4 * SKN]);
            }
            #pragma unroll
            for (int i = 0; i < 4; i++)
                #pragma unroll
                for (int j = 0; j < 8; j++)
                    mma_tf32(acc[i][j], a[i][0], a[i][1], a[i][2], a[i][3],
                             bb[j][0], bb[j][1]);
        }
        __syncthreads();
    }

    #pragma unroll
    for (int i = 0; i < 4; i++) {
        int r0 = o0 + wm + i * 16 + lr;
        int r1 = r0 + 8;
        float bo0 = (r0 < split ? B1[r0] : B2[r0 - split]);
        float bo1 = (r1 < split ? B1[r1] : B2[r1 - split]);
        #pragma unroll
        for (int j = 0; j < 8; j++) {
            int col = n0 + wn + j * 8 + lc * 2;
            float2 v0 = { round_tf32(acc[i][j][0] + bo0), round_tf32(acc[i][j][1] + bo0) };
            float2 v1 = { round_tf32(acc[i][j][2] + bo1), round_tf32(acc[i][j][3] + bo1) };
            *(float2*)&Pb[(size_t)r0 * NHW + col] = v0;
            *(float2*)&Pb[(size_t)r1 * NHW + col] = v1;
        }
    }
    #undef PROJ_LOAD
}

// ---------------------------------------------------------------------------
// Scores: S[n][m] = sum_d Q[d][n] * K[d][m].  A = Q^T (KN layout), B = K (KN).
// Inputs pre-rounded to tf32 -> no cvt. grid: (NHW/128 m, NHW/128 n, NB).
// ---------------------------------------------------------------------------
__global__ void __launch_bounds__(128)
scores_tf32(const float* __restrict__ QK, float* __restrict__ S) {
    const int b  = blockIdx.z;
    const int m0 = blockIdx.x * 128;
    const int n0 = blockIdx.y * 128;
    const float* Qb = QK + (size_t)b * 128 * NHW;           // rows 0..63
    const float* Kb = Qb + (size_t)64 * NHW;                // rows 64..127
    float*       Sb = S + (size_t)b * NHW * NHW;

    __shared__ float sA[2][16 * SKN];
    __shared__ float sB[2][16 * SKN];

    const int tid = threadIdx.x;
    const int lane = tid & 31, wid = tid >> 5;
    const int wm = (wid >> 1) * 64, wn = (wid & 1) * 64;
    const int lr = lane >> 2, lc = lane & 3;

    const int krow0 = tid >> 5, cn4 = tid & 31;
    const unsigned sAu = (unsigned)__cvta_generic_to_shared(&sA[0][0]);
    const unsigned sBu = (unsigned)__cvta_generic_to_shared(&sB[0][0]);

    float acc[4][8][4];
    #pragma unroll
    for (int i = 0; i < 4; i++)
        #pragma unroll
        for (int j = 0; j < 8; j++)
            #pragma unroll
            for (int q = 0; q < 4; q++) acc[i][j][q] = 0.f;

    const int NCH = ND / 16;
    #define SC_LOAD(ch, buf) {                                                        \
        int d0 = (ch) * 16;                                                           \
        _Pragma("unroll")                                                             \
        for (int p = 0; p < 4; p++) {                                                 \
            int kr = krow0 + p * 4;                                                   \
            CPA16(sAu + ((buf) * 16 * SKN + kr * SKN + cn4 * 4) * 4,                  \
                  Qb + (size_t)(d0 + kr) * NHW + n0 + cn4 * 4);                       \
            CPA16(sBu + ((buf) * 16 * SKN + kr * SKN + cn4 * 4) * 4,                  \
                  Kb + (size_t)(d0 + kr) * NHW + m0 + cn4 * 4);                       \
        }                                                                             \
    }

    SC_LOAD(0, 0); CP_COMMIT();
    for (int ch = 0; ch < NCH; ch++) {
        int buf = ch & 1;
        if (ch + 1 < NCH) { SC_LOAD(ch + 1, buf ^ 1); }
        CP_COMMIT();
        CP_WAIT1();
        __syncthreads();
        const float* As = sA[buf];
        const float* Bs = sB[buf];
        #pragma unroll
        for (int ks = 0; ks < 2; ks++) {
            const int kb = ks * 8;
            unsigned a[4][4];
            #pragma unroll
            for (int i = 0; i < 4; i++) {
                const float* ap = As + (kb + lc) * SKN + wm + i * 16 + lr;
                a[i][0] = __float_as_uint(ap[0]);
                a[i][1] = __float_as_uint(ap[8]);
                a[i][2] = __float_as_uint(ap[4 * SKN]);
                a[i][3] = __float_as_uint(ap[4 * SKN + 8]);
            }
            unsigned bb[8][2];
            #pragma unroll
            for (int j = 0; j < 8; j++) {
                const float* bp = Bs + (kb + lc) * SKN + wn + j * 8 + lr;
                bb[j][0] = __float_as_uint(bp[0]);
                bb[j][1] = __float_as_uint(bp[4 * SKN]);
            }
            #pragma unroll
            for (int i = 0; i < 4; i++)
                #pragma unroll
                for (int j = 0; j < 8; j++)
                    mma_tf32(acc[i][j], a[i][0], a[i][1], a[i][2], a[i][3],
                             bb[j][0], bb[j][1]);
        }
        __syncthreads();
    }

    #pragma unroll
    for (int i = 0; i < 4; i++) {
        int r0 = n0 + wm + i * 16 + lr;
        int r1 = r0 + 8;
        #pragma unroll
        for (int j = 0; j < 8; j++) {
            int col = m0 + wn + j * 8 + lc * 2;
            float2 v0 = { acc[i][j][0], acc[i][j][1] };
            float2 v1 = { acc[i][j][2], acc[i][j][3] };
            *(float2*)&Sb[(size_t)r0 * NHW + col] = v0;
            *(float2*)&Sb[(size_t)r1 * NHW + col] = v1;
        }
    }
    #undef SC_LOAD
}

// ---------------------------------------------------------------------------
// Row softmax over m=2304; output rounded to tf32 for the out-GEMM.
// ---------------------------------------------------------------------------
__global__ void softmax_kernel(float* __restrict__ A) {
    float* p = A + (size_t)blockIdx.x * NHW;
    const int tid = threadIdx.x;

    float r[9];
    float mx = -1e30f;
    #pragma unroll
    for (int i = 0; i < 9; i++) {
        r[i] = p[tid + i * 256];
        mx = fmaxf(mx, r[i]);
    }
    __shared__ float red[8];
    #pragma unroll
    for (int off = 16; off > 0; off >>= 1)
        mx = fmaxf(mx, __shfl_xor_sync(0xffffffffu, mx, off));
    if ((tid & 31) == 0) red[tid >> 5] = mx;
    __syncthreads();
    float bm = red[0];
    #pragma unroll
    for (int w = 1; w < 8; w++) bm = fmaxf(bm, red[w]);
    __syncthreads();

    float s = 0.f;
    #pragma unroll
    for (int i = 0; i < 9; i++) { r[i] = __expf(r[i] - bm); s += r[i]; }
    #pragma unroll
    for (int off = 16; off > 0; off >>= 1)
        s += __shfl_xor_sync(0xffffffffu, s, off);
    if ((tid & 31) == 0) red[tid >> 5] = s;
    __syncthreads();
    float bs = 0.f;
    #pragma unroll
    for (int w = 0; w < 8; w++) bs += red[w];

    float inv = 1.f / bs;
    #pragma unroll
    for (int i = 0; i < 9; i++)
        p[tid + i * 256] = round_tf32(r[i] * inv);
}

// ---------------------------------------------------------------------------
// Out: Y[c][n] = gamma * sum_m V[c][m]*A[n][m] + X[c][n].
// A-op = V (RK), B-op = Attn rows-as-n (RK: [n][k]). Pre-rounded -> no cvt.
// grid: (NHW/128 n, NC/128 c, NB).
// ---------------------------------------------------------------------------
__global__ void __launch_bounds__(128)
out_tf32(const float* __restrict__ V, const float* __restrict__ At,
         const float* __restrict__ X, const float* __restrict__ gamma,
         float* __restrict__ Y) {
    const int b  = blockIdx.z;
    const int n0 = blockIdx.x * 128;
    const int c0 = blockIdx.y * 128;
    const float* Vb = V  + (size_t)b * NC * NHW;
    const float* Ab = At + (size_t)b * NHW * NHW;
    const float* Xb = X  + (size_t)b * NC * NHW;
    float*       Yb = Y  + (size_t)b * NC * NHW;

    __shared__ float sA[2][128 * SRK];
    __shared__ float sB[2][128 * SRK];

    const int tid = threadIdx.x;
    const int lane = tid & 31, wid = tid >> 5;
    const int wm = (wid >> 1) * 64, wn = (wid & 1) * 64;
    const int lr = lane >> 2, lc = lane & 3;

    const int arow0 = tid >> 2, ac4 = tid & 3;
    const unsigned sAu = (unsigned)__cvta_generic_to_shared(&sA[0][0]);
    const unsigned sBu = (unsigned)__cvta_generic_to_shared(&sB[0][0]);

    float acc[4][8][4];
    #pragma unroll
    for (int i = 0; i < 4; i++)
        #pragma unroll
        for (int j = 0; j < 8; j++)
            #pragma unroll
            for (int q = 0; q < 4; q++) acc[i][j][q] = 0.f;

    const int NCH = NHW / 16;
    #define OUT_LOAD(ch, buf) {                                                       \
        int m0 = (ch) * 16;                                                           \
        _Pragma("unroll")                                                             \
        for (int p = 0; p < 4; p++) {                                                 \
            int row = arow0 + p * 32;                                                 \
            CPA16(sAu + ((buf) * 128 * SRK + row * SRK + ac4 * 4) * 4,                \
                  Vb + (size_t)(c0 + row) * NHW + m0 + ac4 * 4);                      \
            CPA16(sBu + ((buf) * 128 * SRK + row * SRK + ac4 * 4) * 4,                \
                  Ab + (size_t)(n0 + row) * NHW + m0 + ac4 * 4);                      \
        }                                                                             \
    }

    OUT_LOAD(0, 0); CP_COMMIT();
    for (int ch = 0; ch < NCH; ch++) {
        int buf = ch & 1;
        if (ch + 1 < NCH) { OUT_LOAD(ch + 1, buf ^ 1); }
        CP_COMMIT();
        CP_WAIT1();
        __syncthreads();
        const float* As = sA[buf];
        const float* Bs = sB[buf];
        #pragma unroll
        for (int ks = 0; ks < 2; ks++) {
            const int kb = ks * 8;
            unsigned a[4][4];
            #pragma unroll
            for (int i = 0; i < 4; i++) {
                const float* ap = As + (wm + i * 16 + lr) * SRK + kb + lc;
                a[i][0] = __float_as_uint(ap[0]);
                a[i][1] = __float_as_uint(ap[8 * SRK]);
                a[i][2] = __float_as_uint(ap[4]);
                a[i][3] = __float_as_uint(ap[8 * SRK + 4]);
            }
            unsigned bb[8][2];
            #pragma unroll
            for (int j = 0; j < 8; j++) {
                const float* bp = Bs + (wn + j * 8 + lr) * SRK + kb + lc;
                bb[j][0] = __float_as_uint(bp[0]);
                bb[j][1] = __float_as_uint(bp[4]);
            }
            #pragma unroll
            for (int i = 0; i < 4; i++)
                #pragma unroll
                for (int j = 0; j < 8; j++)
                    mma_tf32(acc[i][j], a[i][0], a[i][1], a[i][2], a[i][3],
                             bb[j][0], bb[j][1]);
        }
        __syncthreads();
    }

    const float g = gamma[0];
    #pragma unroll
    for (int i = 0; i < 4; i++) {
        int r0 = c0 + wm + i * 16 + lr;
        int r1 = r0 + 8;
        #pragma unroll
        for (int j = 0; j < 8; j++) {
            int col = n0 + wn + j * 8 + lc * 2;
            size_t i0 = (size_t)r0 * NHW + col;
            size_t i1 = (size_t)r1 * NHW + col;
            float2 x0 = *(const float2*)&Xb[i0];
            float2 x1 = *(const float2*)&Xb[i1];
            float2 v0 = { g * acc[i][j][0] + x0.x, g * acc[i][j][1] + x0.y };
            float2 v1 = { g * acc[i][j][2] + x1.x, g * acc[i][j][3] + x1.y };
            *(float2*)&Yb[i0] = v0;
            *(float2*)&Yb[i1] = v1;
        }
    }
    #undef OUT_LOAD
}

// ---------------------------------------------------------------------------
extern "C" void kernel_launch(void* const* d_in, const int* in_sizes, int n_in,
                              void* d_out, int out_size) {
    const float* X     = (const float*)d_in[0];
    const float* Wq    = (const float*)d_in[1];
    const float* bq    = (const float*)d_in[2];
    const float* Wk    = (const float*)d_in[3];
    const float* bk    = (const float*)d_in[4];
    const float* Wv    = (const float*)d_in[5];
    const float* bv    = (const float*)d_in[6];
    const float* gamma = (const float*)d_in[7];
    float* Y = (float*)d_out;

    float *QK, *V, *A;
    cudaGetSymbolAddress((void**)&QK, g_QK);
    cudaGetSymbolAddress((void**)&V,  g_V);
    cudaGetSymbolAddress((void**)&A,  g_A);

    // Q+K stacked projection (rows 0..63 = Q, 64..127 = K)
    proj_tf32<<<dim3(NHW / 128, 1, NB), 128>>>(X, Wq, bq, Wk, bk, 64, QK);
    // V projection
    proj_tf32<<<dim3(NHW / 128, NC / 128, NB), 128>>>(X, Wv, bv, Wv, bv, NC, V);
    // S = Q^T K
    scores_tf32<<<dim3(NHW / 128, NHW / 128, NB), 128>>>(QK, A);
    // softmax rows (rounds output to tf32)
    softmax_kernel<<<NB * NHW, 256>>>(A);
    // Y = gamma * V A^T + X
    out_tf32<<<dim3(NHW / 128, NC / 128, NB), 128>>>(V, A, X, gamma, Y);
}

// round 5
// speedup vs baseline: 4.1958x; 1.0528x over previous
#include <cuda_runtime.h>
#include <cstdint>

// DANet spatial attention — TF32 tensor-core GEMMs + fused (softmax-free) attention.
// B=16, C=512, HW=2304, d=64.
// scores writes exp(S) directly + per-row partial sums; out normalizes per column.

#define NB 16
#define NC 512
#define NHW 2304
#define ND 64
#define NMT 18              // m-tiles per row (2304/128)

__device__ float g_QK[(size_t)NB * 128 * NHW];   // rows 0..63 = Q, 64..127 = K
__device__ float g_V [(size_t)NB * NC  * NHW];
__device__ float g_A [(size_t)NB * NHW * NHW];   // exp(S), tf32-rounded
__device__ float g_psum[(size_t)NB * NMT * NHW]; // per (b, mtile, row) partial sums
__device__ float g_inv [(size_t)NB * NHW];       // 1 / rowsum

// ---------------------------------------------------------------------------
__device__ __forceinline__ unsigned cvt_tf32(float x) {
    unsigned u; asm("cvt.rna.tf32.f32 %0, %1;" : "=r"(u) : "f"(x)); return u;
}
__device__ __forceinline__ float round_tf32(float x) {
    return __uint_as_float(cvt_tf32(x));
}
__device__ __forceinline__ void mma_tf32(float c[4],
                                         unsigned a0, unsigned a1, unsigned a2, unsigned a3,
                                         unsigned b0, unsigned b1) {
    asm volatile(
        "mma.sync.aligned.m16n8k8.row.col.f32.tf32.tf32.f32 "
        "{%0,%1,%2,%3}, {%4,%5,%6,%7}, {%8,%9}, {%0,%1,%2,%3};"
        : "+f"(c[0]), "+f"(c[1]), "+f"(c[2]), "+f"(c[3])
        : "r"(a0), "r"(a1), "r"(a2), "r"(a3), "r"(b0), "r"(b1));
}
#define CPA16(dst, src) asm volatile("cp.async.ca.shared.global [%0], [%1], 16;\n" :: "r"(dst), "l"(src))
#define CP_COMMIT()     asm volatile("cp.async.commit_group;\n")
#define CP_WAIT1()      asm volatile("cp.async.wait_group 1;\n")

#define SRK 20
#define SKN 136

// ---------------------------------------------------------------------------
// Projection: P[o][n] = round_tf32( sum_c W[o][c] * X[c][n] + bias[o] )
// ---------------------------------------------------------------------------
__global__ void __launch_bounds__(128)
proj_tf32(const float* __restrict__ X,
          const float* __restrict__ W1, const float* __restrict__ B1,
          const float* __restrict__ W2, const float* __restrict__ B2,
          int split, float* __restrict__ P) {
    const int b  = blockIdx.z;
    const int n0 = blockIdx.x * 128;
    const int o0 = blockIdx.y * 128;
    const int O  = gridDim.y * 128;
    const float* Xb = X + (size_t)b * NC * NHW;
    float*       Pb = P + (size_t)b * O * NHW;

    __shared__ float sA[2][128 * SRK];
    __shared__ float sB[2][16 * SKN];

    const int tid = threadIdx.x;
    const int lane = tid & 31, wid = tid >> 5;
    const int wm = (wid >> 1) * 64, wn = (wid & 1) * 64;
    const int lr = lane >> 2, lc = lane & 3;

    const int arow0 = tid >> 2, ac4 = tid & 3;
    const int brow0 = tid >> 5, bn4 = tid & 31;
    const float* Arows[4];
    #pragma unroll
    for (int p = 0; p < 4; p++) {
        int row = o0 + arow0 + p * 32;
        Arows[p] = (row < split ? W1 + (size_t)row * NC
                                : W2 + (size_t)(row - split) * NC);
    }
    const unsigned sAu = (unsigned)__cvta_generic_to_shared(&sA[0][0]);
    const unsigned sBu = (unsigned)__cvta_generic_to_shared(&sB[0][0]);

    float acc[4][8][4];
    #pragma unroll
    for (int i = 0; i < 4; i++)
        #pragma unroll
        for (int j = 0; j < 8; j++)
            #pragma unroll
            for (int q = 0; q < 4; q++) acc[i][j][q] = 0.f;

    const int NCH = NC / 16;
    #define PROJ_LOAD(ch, buf) {                                                      \
        int c0 = (ch) * 16;                                                           \
        _Pragma("unroll")                                                             \
        for (int p = 0; p < 4; p++) {                                                 \
            int row = arow0 + p * 32;                                                 \
            CPA16(sAu + ((buf) * 128 * SRK + row * SRK + ac4 * 4) * 4,                \
                  Arows[p] + c0 + ac4 * 4);                                           \
            int kr = brow0 + p * 4;                                                   \
            CPA16(sBu + ((buf) * 16 * SKN + kr * SKN + bn4 * 4) * 4,                  \
                  Xb + (size_t)(c0 + kr) * NHW + n0 + bn4 * 4);                       \
        }                                                                             \
    }

    PROJ_LOAD(0, 0); CP_COMMIT();
    for (int ch = 0; ch < NCH; ch++) {
        int buf = ch & 1;
        if (ch + 1 < NCH) { PROJ_LOAD(ch + 1, buf ^ 1); }
        CP_COMMIT();
        CP_WAIT1();
        __syncthreads();
        const float* As = sA[buf];
        const float* Bs = sB[buf];
        #pragma unroll
        for (int ks = 0; ks < 2; ks++) {
            const int kb = ks * 8;
            unsigned a[4][4];
            #pragma unroll
            for (int i = 0; i < 4; i++) {
                const float* ap = As + (wm + i * 16 + lr) * SRK + kb + lc;
                a[i][0] = cvt_tf32(ap[0]);
                a[i][1] = cvt_tf32(ap[8 * SRK]);
                a[i][2] = cvt_tf32(ap[4]);
                a[i][3] = cvt_tf32(ap[8 * SRK + 4]);
            }
            unsigned bb[8][2];
            #pragma unroll
            for (int j = 0; j < 8; j++) {
                const float* bp = Bs + (kb + lc) * SKN + wn + j * 8 + lr;
                bb[j][0] = cvt_tf32(bp[0]);
                bb[j][1] = cvt_tf32(bp[4 * SKN]);
            }
            #pragma unroll
            for (int i = 0; i < 4; i++)
                #pragma unroll
                for (int j = 0; j < 8; j++)
                    mma_tf32(acc[i][j], a[i][0], a[i][1], a[i][2], a[i][3],
                             bb[j][0], bb[j][1]);
        }
        __syncthreads();
    }

    #pragma unroll
    for (int i = 0; i < 4; i++) {
        int r0 = o0 + wm + i * 16 + lr;
        int r1 = r0 + 8;
        float bo0 = (r0 < split ? B1[r0] : B2[r0 - split]);
        float bo1 = (r1 < split ? B1[r1] : B2[r1 - split]);
        #pragma unroll
        for (int j = 0; j < 8; j++) {
            int col = n0 + wn + j * 8 + lc * 2;
            float2 v0 = { round_tf32(acc[i][j][0] + bo0), round_tf32(acc[i][j][1] + bo0) };
            float2 v1 = { round_tf32(acc[i][j][2] + bo1), round_tf32(acc[i][j][3] + bo1) };
            *(float2*)&Pb[(size_t)r0 * NHW + col] = v0;
            *(float2*)&Pb[(size_t)r1 * NHW + col] = v1;
        }
    }
    #undef PROJ_LOAD
}

// ---------------------------------------------------------------------------
// Scores+exp: E[n][m] = round_tf32(exp(sum_d Q[d][n]*K[d][m])), plus per-row
// partial sums -> g_psum[b][mtile][n]. No max-subtraction needed (|s| small).
// ---------------------------------------------------------------------------
__global__ void __launch_bounds__(128)
scores_tf32(const float* __restrict__ QK, float* __restrict__ E,
            float* __restrict__ psum) {
    const int b  = blockIdx.z;
    const int mt = blockIdx.x;
    const int m0 = mt * 128;
    const int n0 = blockIdx.y * 128;
    const float* Qb = QK + (size_t)b * 128 * NHW;
    const float* Kb = Qb + (size_t)64 * NHW;
    float*       Eb = E + (size_t)b * NHW * NHW;

    __shared__ float sA[2][16 * SKN];
    __shared__ float sB[2][16 * SKN];
    __shared__ float srow[128];

    const int tid = threadIdx.x;
    const int lane = tid & 31, wid = tid >> 5;
    const int wm = (wid >> 1) * 64, wn = (wid & 1) * 64;
    const int lr = lane >> 2, lc = lane & 3;

    const int krow0 = tid >> 5, cn4 = tid & 31;
    const unsigned sAu = (unsigned)__cvta_generic_to_shared(&sA[0][0]);
    const unsigned sBu = (unsigned)__cvta_generic_to_shared(&sB[0][0]);

    float acc[4][8][4];
    #pragma unroll
    for (int i = 0; i < 4; i++)
        #pragma unroll
        for (int j = 0; j < 8; j++)
            #pragma unroll
            for (int q = 0; q < 4; q++) acc[i][j][q] = 0.f;

    const int NCH = ND / 16;
    #define SC_LOAD(ch, buf) {                                                        \
        int d0 = (ch) * 16;                                                           \
        _Pragma("unroll")                                                             \
        for (int p = 0; p < 4; p++) {                                                 \
            int kr = krow0 + p * 4;                                                   \
            CPA16(sAu + ((buf) * 16 * SKN + kr * SKN + cn4 * 4) * 4,                  \
                  Qb + (size_t)(d0 + kr) * NHW + n0 + cn4 * 4);                       \
            CPA16(sBu + ((buf) * 16 * SKN + kr * SKN + cn4 * 4) * 4,                  \
                  Kb + (size_t)(d0 + kr) * NHW + m0 + cn4 * 4);                       \
        }                                                                             \
    }

    SC_LOAD(0, 0); CP_COMMIT();
    for (int ch = 0; ch < NCH; ch++) {
        int buf = ch & 1;
        if (ch + 1 < NCH) { SC_LOAD(ch + 1, buf ^ 1); }
        CP_COMMIT();
        CP_WAIT1();
        __syncthreads();
        const float* As = sA[buf];
        const float* Bs = sB[buf];
        #pragma unroll
        for (int ks = 0; ks < 2; ks++) {
            const int kb = ks * 8;
            unsigned a[4][4];
            #pragma unroll
            for (int i = 0; i < 4; i++) {
                const float* ap = As + (kb + lc) * SKN + wm + i * 16 + lr;
                a[i][0] = __float_as_uint(ap[0]);
                a[i][1] = __float_as_uint(ap[8]);
                a[i][2] = __float_as_uint(ap[4 * SKN]);
                a[i][3] = __float_as_uint(ap[4 * SKN + 8]);
            }
            unsigned bb[8][2];
            #pragma unroll
            for (int j = 0; j < 8; j++) {
                const float* bp = Bs + (kb + lc) * SKN + wn + j * 8 + lr;
                bb[j][0] = __float_as_uint(bp[0]);
                bb[j][1] = __float_as_uint(bp[4 * SKN]);
            }
            #pragma unroll
            for (int i = 0; i < 4; i++)
                #pragma unroll
                for (int j = 0; j < 8; j++)
                    mma_tf32(acc[i][j], a[i][0], a[i][1], a[i][2], a[i][3],
                             bb[j][0], bb[j][1]);
        }
        __syncthreads();
    }

    // epilogue: exp, store, per-row partial sums
    float rs0[4], rs1[4];
    #pragma unroll
    for (int i = 0; i < 4; i++) {
        int r0 = n0 + wm + i * 16 + lr;
        int r1 = r0 + 8;
        float s0 = 0.f, s1 = 0.f;
        #pragma unroll
        for (int j = 0; j < 8; j++) {
            int col = m0 + wn + j * 8 + lc * 2;
            float e0 = round_tf32(__expf(acc[i][j][0]));
            float e1 = round_tf32(__expf(acc[i][j][1]));
            float e2 = round_tf32(__expf(acc[i][j][2]));
            float e3 = round_tf32(__expf(acc[i][j][3]));
            float2 v0 = { e0, e1 };
            float2 v1 = { e2, e3 };
            *(float2*)&Eb[(size_t)r0 * NHW + col] = v0;
            *(float2*)&Eb[(size_t)r1 * NHW + col] = v1;
            s0 += e0 + e1;
            s1 += e2 + e3;
        }
        s0 += __shfl_xor_sync(0xffffffffu, s0, 1);
        s0 += __shfl_xor_sync(0xffffffffu, s0, 2);
        s1 += __shfl_xor_sync(0xffffffffu, s1, 1);
        s1 += __shfl_xor_sync(0xffffffffu, s1, 2);
        rs0[i] = s0; rs1[i] = s1;
        if ((wid & 1) == 0 && lc == 0) {
            srow[wm + i * 16 + lr]     = s0;
            srow[wm + i * 16 + lr + 8] = s1;
        }
    }
    __syncthreads();
    if ((wid & 1) == 1 && lc == 0) {
        float* ps = psum + ((size_t)(b * NMT + mt)) * NHW + n0;
        #pragma unroll
        for (int i = 0; i < 4; i++) {
            int lrow = wm + i * 16 + lr;
            ps[lrow]     = srow[lrow]     + rs0[i];
            ps[lrow + 8] = srow[lrow + 8] + rs1[i];
        }
    }
    #undef SC_LOAD
}

// ---------------------------------------------------------------------------
// Combine partial sums -> 1/rowsum.  idx over NB*NHW.
// ---------------------------------------------------------------------------
__global__ void invsum_kernel(const float* __restrict__ psum, float* __restrict__ inv) {
    int idx = blockIdx.x * 256 + threadIdx.x;
    if (idx >= NB * NHW) return;
    int b = idx / NHW, n = idx - b * NHW;
    const float* ps = psum + (size_t)b * NMT * NHW + n;
    float s = 0.f;
    #pragma unroll
    for (int mt = 0; mt < NMT; mt++) s += ps[(size_t)mt * NHW];
    inv[idx] = 1.f / s;
}

// ---------------------------------------------------------------------------
// Out: Y[c][n] = gamma * (sum_m V[c][m]*E[n][m]) * inv[n] + X[c][n].
// grid: (NC/128 c, NHW/128 n, NB)  -- c fastest so same-n blocks share E in L2.
// ---------------------------------------------------------------------------
__global__ void __launch_bounds__(128)
out_tf32(const float* __restrict__ V, const float* __restrict__ E,
         const float* __restrict__ inv, const float* __restrict__ X,
         const float* __restrict__ gamma, float* __restrict__ Y) {
    const int b  = blockIdx.z;
    const int c0 = blockIdx.x * 128;
    const int n0 = blockIdx.y * 128;
    const float* Vb = V + (size_t)b * NC * NHW;
    const float* Ab = E + (size_t)b * NHW * NHW;
    const float* Xb = X + (size_t)b * NC * NHW;
    const float* invb = inv + (size_t)b * NHW;
    float*       Yb = Y + (size_t)b * NC * NHW;

    __shared__ float sA[2][128 * SRK];
    __shared__ float sB[2][128 * SRK];

    const int tid = threadIdx.x;
    const int lane = tid & 31, wid = tid >> 5;
    const int wm = (wid >> 1) * 64, wn = (wid & 1) * 64;
    const int lr = lane >> 2, lc = lane & 3;

    const int arow0 = tid >> 2, ac4 = tid & 3;
    const unsigned sAu = (unsigned)__cvta_generic_to_shared(&sA[0][0]);
    const unsigned sBu = (unsigned)__cvta_generic_to_shared(&sB[0][0]);

    float acc[4][8][4];
    #pragma unroll
    for (int i = 0; i < 4; i++)
        #pragma unroll
        for (int j = 0; j < 8; j++)
            #pragma unroll
            for (int q = 0; q < 4; q++) acc[i][j][q] = 0.f;

    const int NCH = NHW / 16;
    #define OUT_LOAD(ch, buf) {                                                       \
        int m0 = (ch) * 16;                                                           \
        _Pragma("unroll")                                                             \
        for (int p = 0; p < 4; p++) {                                                 \
            int row = arow0 + p * 32;                                                 \
            CPA16(sAu + ((buf) * 128 * SRK + row * SRK + ac4 * 4) * 4,                \
                  Vb + (size_t)(c0 + row) * NHW + m0 + ac4 * 4);                      \
            CPA16(sBu + ((buf) * 128 * SRK + row * SRK + ac4 * 4) * 4,                \
                  Ab + (size_t)(n0 + row) * NHW + m0 + ac4 * 4);                      \
        }                                                                             \
    }

    OUT_LOAD(0, 0); CP_COMMIT();
    for (int ch = 0; ch < NCH; ch++) {
        int buf = ch & 1;
        if (ch + 1 < NCH) { OUT_LOAD(ch + 1, buf ^ 1); }
        CP_COMMIT();
        CP_WAIT1();
        __syncthreads();
        const float* As = sA[buf];
        const float* Bs = sB[buf];
        #pragma unroll
        for (int ks = 0; ks < 2; ks++) {
            const int kb = ks * 8;
            unsigned a[4][4];
            #pragma unroll
            for (int i = 0; i < 4; i++) {
                const float* ap = As + (wm + i * 16 + lr) * SRK + kb + lc;
                a[i][0] = __float_as_uint(ap[0]);
                a[i][1] = __float_as_uint(ap[8 * SRK]);
                a[i][2] = __float_as_uint(ap[4]);
                a[i][3] = __float_as_uint(ap[8 * SRK + 4]);
            }
            unsigned bb[8][2];
            #pragma unroll
            for (int j = 0; j < 8; j++) {
                const float* bp = Bs + (wn + j * 8 + lr) * SRK + kb + lc;
                bb[j][0] = __float_as_uint(bp[0]);
                bb[j][1] = __float_as_uint(bp[4]);
            }
            #pragma unroll
            for (int i = 0; i < 4; i++)
                #pragma unroll
                for (int j = 0; j < 8; j++)
                    mma_tf32(acc[i][j], a[i][0], a[i][1], a[i][2], a[i][3],
                             bb[j][0], bb[j][1]);
        }
        __syncthreads();
    }

    const float g = gamma[0];
    #pragma unroll
    for (int i = 0; i < 4; i++) {
        int r0 = c0 + wm + i * 16 + lr;
        int r1 = r0 + 8;
        #pragma unroll
        for (int j = 0; j < 8; j++) {
            int col = n0 + wn + j * 8 + lc * 2;
            float2 iv = *(const float2*)&invb[col];
            size_t i0 = (size_t)r0 * NHW + col;
            size_t i1 = (size_t)r1 * NHW + col;
            float2 x0 = *(const float2*)&Xb[i0];
            float2 x1 = *(const float2*)&Xb[i1];
            float2 v0 = { g * acc[i][j][0] * iv.x + x0.x, g * acc[i][j][1] * iv.y + x0.y };
            float2 v1 = { g * acc[i][j][2] * iv.x + x1.x, g * acc[i][j][3] * iv.y + x1.y };
            *(float2*)&Yb[i0] = v0;
            *(float2*)&Yb[i1] = v1;
        }
    }
    #undef OUT_LOAD
}

// ---------------------------------------------------------------------------
extern "C" void kernel_launch(void* const* d_in, const int* in_sizes, int n_in,
                              void* d_out, int out_size) {
    const float* X     = (const float*)d_in[0];
    const float* Wq    = (const float*)d_in[1];
    const float* bq    = (const float*)d_in[2];
    const float* Wk    = (const float*)d_in[3];
    const float* bk    = (const float*)d_in[4];
    const float* Wv    = (const float*)d_in[5];
    const float* bv    = (const float*)d_in[6];
    const float* gamma = (const float*)d_in[7];
    float* Y = (float*)d_out;

    float *QK, *V, *A, *PS, *IV;
    cudaGetSymbolAddress((void**)&QK, g_QK);
    cudaGetSymbolAddress((void**)&V,  g_V);
    cudaGetSymbolAddress((void**)&A,  g_A);
    cudaGetSymbolAddress((void**)&PS, g_psum);
    cudaGetSymbolAddress((void**)&IV, g_inv);

    proj_tf32<<<dim3(NHW / 128, 1, NB), 128>>>(X, Wq, bq, Wk, bk, 64, QK);
    proj_tf32<<<dim3(NHW / 128, NC / 128, NB), 128>>>(X, Wv, bv, Wv, bv, NC, V);
    scores_tf32<<<dim3(NHW / 128, NHW / 128, NB), 128>>>(QK, A, PS);
    invsum_kernel<<<(NB * NHW + 255) / 256, 256>>>(PS, IV);
    out_tf32<<<dim3(NC / 128, NHW / 128, NB), 128>>>(V, A, IV, X, gamma, Y);
}

// round 6
// speedup vs baseline: 4.7363x; 1.1288x over previous
#include <cuda_runtime.h>
#include <cuda_bf16.h>
#include <cstdint>

// DANet spatial attention — TF32 projections + bf16 (m16n8k16) attention GEMMs.
// B=16, C=512, HW=2304, d=64. Softmax-free: scores emit exp(S) bf16 + row sums.

#define NB 16
#define NC 512
#define NHW 2304
#define ND 64
#define NMT 18

__device__ __nv_bfloat16 g_Qt[(size_t)NB * NHW * ND];    // [b][n][d]
__device__ __nv_bfloat16 g_Kt[(size_t)NB * NHW * ND];    // [b][m][d]
__device__ __nv_bfloat16 g_Vb[(size_t)NB * NC * NHW];    // [b][c][m]
__device__ __nv_bfloat16 g_Eb[(size_t)NB * NHW * NHW];   // [b][n][m] = exp(S)
__device__ float g_psum[(size_t)NB * NMT * NHW];
__device__ float g_inv [(size_t)NB * NHW];

// ---------------------------------------------------------------------------
__device__ __forceinline__ unsigned cvt_tf32(float x) {
    unsigned u; asm("cvt.rna.tf32.f32 %0, %1;" : "=r"(u) : "f"(x)); return u;
}
__device__ __forceinline__ void mma_tf32(float c[4],
                                         unsigned a0, unsigned a1, unsigned a2, unsigned a3,
                                         unsigned b0, unsigned b1) {
    asm volatile(
        "mma.sync.aligned.m16n8k8.row.col.f32.tf32.tf32.f32 "
        "{%0,%1,%2,%3}, {%4,%5,%6,%7}, {%8,%9}, {%0,%1,%2,%3};"
        : "+f"(c[0]), "+f"(c[1]), "+f"(c[2]), "+f"(c[3])
        : "r"(a0), "r"(a1), "r"(a2), "r"(a3), "r"(b0), "r"(b1));
}
__device__ __forceinline__ void mma_bf16(float c[4],
                                         unsigned a0, unsigned a1, unsigned a2, unsigned a3,
                                         unsigned b0, unsigned b1) {
    asm volatile(
        "mma.sync.aligned.m16n8k16.row.col.f32.bf16.bf16.f32 "
        "{%0,%1,%2,%3}, {%4,%5,%6,%7}, {%8,%9}, {%0,%1,%2,%3};"
        : "+f"(c[0]), "+f"(c[1]), "+f"(c[2]), "+f"(c[3])
        : "r"(a0), "r"(a1), "r"(a2), "r"(a3), "r"(b0), "r"(b1));
}
#define CPA16(dst, src) asm volatile("cp.async.ca.shared.global [%0], [%1], 16;\n" :: "r"(dst), "l"(src))
#define CP_COMMIT()     asm volatile("cp.async.commit_group;\n")
#define CP_WAIT1()      asm volatile("cp.async.wait_group 1;\n")
#define CP_WAIT0()      asm volatile("cp.async.wait_group 0;\n")

#define SRK 20     // fp32 tile stride [row][16k]
#define SKN 136    // fp32 tile stride [16k][128cols]
#define SB64 72    // bf16 tile stride [row][64k]
#define SB32 40    // bf16 tile stride [row][32k]

// ---------------------------------------------------------------------------
// Projection (TF32 mainloop). QKT=true: emit transposed bf16 Qt/Kt.
//            QKT=false: emit bf16 V [c][m].
// ---------------------------------------------------------------------------
template<bool QKT>
__global__ void __launch_bounds__(128)
proj_tf32(const float* __restrict__ X,
          const float* __restrict__ W1, const float* __restrict__ B1,
          const float* __restrict__ W2, const float* __restrict__ B2,
          int split, __nv_bfloat16* __restrict__ Pv,
          __nv_bfloat16* __restrict__ Qt, __nv_bfloat16* __restrict__ Kt) {
    const int b  = blockIdx.z;
    const int n0 = blockIdx.x * 128;
    const int o0 = blockIdx.y * 128;
    const float* Xb = X + (size_t)b * NC * NHW;

    __shared__ float sA[2][128 * SRK];
    __shared__ float sB[2][16 * SKN];

    const int tid = threadIdx.x;
    const int lane = tid & 31, wid = tid >> 5;
    const int wm = (wid >> 1) * 64, wn = (wid & 1) * 64;
    const int lr = lane >> 2, lc = lane & 3;

    const int arow0 = tid >> 2, ac4 = tid & 3;
    const int brow0 = tid >> 5, bn4 = tid & 31;
    const float* Arows[4];
    #pragma unroll
    for (int p = 0; p < 4; p++) {
        int row = o0 + arow0 + p * 32;
        Arows[p] = (row < split ? W1 + (size_t)row * NC
                                : W2 + (size_t)(row - split) * NC);
    }
    const unsigned sAu = (unsigned)__cvta_generic_to_shared(&sA[0][0]);
    const unsigned sBu = (unsigned)__cvta_generic_to_shared(&sB[0][0]);

    float acc[4][8][4];
    #pragma unroll
    for (int i = 0; i < 4; i++)
        #pragma unroll
        for (int j = 0; j < 8; j++)
            #pragma unroll
            for (int q = 0; q < 4; q++) acc[i][j][q] = 0.f;

    const int NCH = NC / 16;
    #define PROJ_LOAD(ch, buf) {                                                      \
        int c0 = (ch) * 16;                                                           \
        _Pragma("unroll")                                                             \
        for (int p = 0; p < 4; p++) {                                                 \
            int row = arow0 + p * 32;                                                 \
            CPA16(sAu + ((buf) * 128 * SRK + row * SRK + ac4 * 4) * 4,                \
                  Arows[p] + c0 + ac4 * 4);                                           \
            int kr = brow0 + p * 4;                                                   \
            CPA16(sBu + ((buf) * 16 * SKN + kr * SKN + bn4 * 4) * 4,                  \
                  Xb + (size_t)(c0 + kr) * NHW + n0 + bn4 * 4);                       \
        }                                                                             \
    }

    PROJ_LOAD(0, 0); CP_COMMIT();
    for (int ch = 0; ch < NCH; ch++) {
        int buf = ch & 1;
        if (ch + 1 < NCH) { PROJ_LOAD(ch + 1, buf ^ 1); }
        CP_COMMIT();
        CP_WAIT1();
        __syncthreads();
        const float* As = sA[buf];
        const float* Bs = sB[buf];
        #pragma unroll
        for (int ks = 0; ks < 2; ks++) {
            const int kb = ks * 8;
            unsigned a[4][4];
            #pragma unroll
            for (int i = 0; i < 4; i++) {
                const float* ap = As + (wm + i * 16 + lr) * SRK + kb + lc;
                a[i][0] = cvt_tf32(ap[0]);
                a[i][1] = cvt_tf32(ap[8 * SRK]);
                a[i][2] = cvt_tf32(ap[4]);
                a[i][3] = cvt_tf32(ap[8 * SRK + 4]);
            }
            unsigned bb[8][2];
            #pragma unroll
            for (int j = 0; j < 8; j++) {
                const float* bp = Bs + (kb + lc) * SKN + wn + j * 8 + lr;
                bb[j][0] = cvt_tf32(bp[0]);
                bb[j][1] = cvt_tf32(bp[4 * SKN]);
            }
            #pragma unroll
            for (int i = 0; i < 4; i++)
                #pragma unroll
                for (int j = 0; j < 8; j++)
                    mma_tf32(acc[i][j], a[i][0], a[i][1], a[i][2], a[i][3],
                             bb[j][0], bb[j][1]);
        }
        __syncthreads();
    }

    if (QKT) {
        // transposed bf16 stores: Qt[n][d] (rows<64), Kt[m][d] (rows>=64)
        __nv_bfloat16* Qb = Qt + (size_t)b * NHW * ND;
        __nv_bfloat16* Kb = Kt + (size_t)b * NHW * ND;
        #pragma unroll
        for (int i = 0; i < 4; i++) {
            int r0 = o0 + wm + i * 16 + lr;
            int r1 = r0 + 8;
            float bo0 = (r0 < split ? B1[r0] : B2[r0 - split]);
            float bo1 = (r1 < split ? B1[r1] : B2[r1 - split]);
            __nv_bfloat16* P0 = (r0 < split ? Qb : Kb);
            __nv_bfloat16* P1 = (r1 < split ? Qb : Kb);
            int rr0 = (r0 < split ? r0 : r0 - split);
            int rr1 = (r1 < split ? r1 : r1 - split);
            #pragma unroll
            for (int j = 0; j < 8; j++) {
                int col = n0 + wn + j * 8 + lc * 2;
                P0[(size_t)col * ND + rr0]       = __float2bfloat16(acc[i][j][0] + bo0);
                P0[(size_t)(col + 1) * ND + rr0] = __float2bfloat16(acc[i][j][1] + bo0);
                P1[(size_t)col * ND + rr1]       = __float2bfloat16(acc[i][j][2] + bo1);
                P1[(size_t)(col + 1) * ND + rr1] = __float2bfloat16(acc[i][j][3] + bo1);
            }
        }
    } else {
        __nv_bfloat16* Pb = Pv + (size_t)b * NC * NHW;
        #pragma unroll
        for (int i = 0; i < 4; i++) {
            int r0 = o0 + wm + i * 16 + lr;
            int r1 = r0 + 8;
            float bo0 = B1[r0];
            float bo1 = B1[r1];
            #pragma unroll
            for (int j = 0; j < 8; j++) {
                int col = n0 + wn + j * 8 + lc * 2;
                __nv_bfloat162 v0 = __floats2bfloat162_rn(acc[i][j][0] + bo0, acc[i][j][1] + bo0);
                __nv_bfloat162 v1 = __floats2bfloat162_rn(acc[i][j][2] + bo1, acc[i][j][3] + bo1);
                *(__nv_bfloat162*)&Pb[(size_t)r0 * NHW + col] = v0;
                *(__nv_bfloat162*)&Pb[(size_t)r1 * NHW + col] = v1;
            }
        }
    }
    #undef PROJ_LOAD
}

// ---------------------------------------------------------------------------
// Scores+exp (bf16): E[n][m] = bf16(exp(sum_d Qt[n][d]*Kt[m][d])) + row psums.
// Whole k=64 in one smem pass (no k-pipeline). grid (18 m, 18 n, NB), 128 thr.
// ---------------------------------------------------------------------------
__global__ void __launch_bounds__(128)
scores_bf16(const __nv_bfloat16* __restrict__ Qt, const __nv_bfloat16* __restrict__ Kt,
            __nv_bfloat16* __restrict__ E, float* __restrict__ psum) {
    const int b  = blockIdx.z;
    const int mt = blockIdx.x;
    const int m0 = mt * 128;
    const int n0 = blockIdx.y * 128;
    const __nv_bfloat16* Qb = Qt + (size_t)b * NHW * ND;
    const __nv_bfloat16* Kb = Kt + (size_t)b * NHW * ND;
    __nv_bfloat16*       Eb = E + (size_t)b * NHW * NHW;

    __shared__ __nv_bfloat16 sQ[128 * SB64];
    __shared__ __nv_bfloat16 sK[128 * SB64];
    __shared__ float srow[128];

    const int tid = threadIdx.x;
    const int lane = tid & 31, wid = tid >> 5;
    const int wm = (wid >> 1) * 64, wn = (wid & 1) * 64;
    const int lr = lane >> 2, lc = lane & 3;

    const unsigned sQu = (unsigned)__cvta_generic_to_shared(&sQ[0]);
    const unsigned sKu = (unsigned)__cvta_generic_to_shared(&sK[0]);

    // load both 128x64 bf16 tiles; thread tid handles row tid (8x16B each)
    #pragma unroll
    for (int p = 0; p < 8; p++) {
        CPA16(sQu + (tid * SB64 + p * 8) * 2, Qb + (size_t)(n0 + tid) * ND + p * 8);
        CPA16(sKu + (tid * SB64 + p * 8) * 2, Kb + (size_t)(m0 + tid) * ND + p * 8);
    }
    CP_COMMIT();

    float acc[4][8][4];
    #pragma unroll
    for (int i = 0; i < 4; i++)
        #pragma unroll
        for (int j = 0; j < 8; j++)
            #pragma unroll
            for (int q = 0; q < 4; q++) acc[i][j][q] = 0.f;

    CP_WAIT0();
    __syncthreads();

    #pragma unroll
    for (int t = 0; t < 4; t++) {
        const int kb = t * 16 + 2 * lc;
        unsigned a[4][4];
        #pragma unroll
        for (int i = 0; i < 4; i++) {
            int base = (wm + i * 16 + lr) * SB64 + kb;
            a[i][0] = *(const unsigned*)&sQ[base];
            a[i][1] = *(const unsigned*)&sQ[base + 8 * SB64];
            a[i][2] = *(const unsigned*)&sQ[base + 8];
            a[i][3] = *(const unsigned*)&sQ[base + 8 * SB64 + 8];
        }
        unsigned bb[8][2];
        #pragma unroll
        for (int j = 0; j < 8; j++) {
            int base = (wn + j * 8 + lr) * SB64 + kb;
            bb[j][0] = *(const unsigned*)&sK[base];
            bb[j][1] = *(const unsigned*)&sK[base + 8];
        }
        #pragma unroll
        for (int i = 0; i < 4; i++)
            #pragma unroll
            for (int j = 0; j < 8; j++)
                mma_bf16(acc[i][j], a[i][0], a[i][1], a[i][2], a[i][3],
                         bb[j][0], bb[j][1]);
    }

    // epilogue: exp -> bf16, store, per-row partial sums of the *rounded* values
    float rs0[4], rs1[4];
    #pragma unroll
    for (int i = 0; i < 4; i++) {
        int r0 = n0 + wm + i * 16 + lr;
        int r1 = r0 + 8;
        float s0 = 0.f, s1 = 0.f;
        #pragma unroll
        for (int j = 0; j < 8; j++) {
            int col = m0 + wn + j * 8 + lc * 2;
            __nv_bfloat162 h0 = __floats2bfloat162_rn(__expf(acc[i][j][0]), __expf(acc[i][j][1]));
            __nv_bfloat162 h1 = __floats2bfloat162_rn(__expf(acc[i][j][2]), __expf(acc[i][j][3]));
            *(__nv_bfloat162*)&Eb[(size_t)r0 * NHW + col] = h0;
            *(__nv_bfloat162*)&Eb[(size_t)r1 * NHW + col] = h1;
            float2 f0 = __bfloat1622float2(h0);
            float2 f1 = __bfloat1622float2(h1);
            s0 += f0.x + f0.y;
            s1 += f1.x + f1.y;
        }
        s0 += __shfl_xor_sync(0xffffffffu, s0, 1);
        s0 += __shfl_xor_sync(0xffffffffu, s0, 2);
        s1 += __shfl_xor_sync(0xffffffffu, s1, 1);
        s1 += __shfl_xor_sync(0xffffffffu, s1, 2);
        rs0[i] = s0; rs1[i] = s1;
        if ((wid & 1) == 0 && lc == 0) {
            srow[wm + i * 16 + lr]     = s0;
            srow[wm + i * 16 + lr + 8] = s1;
        }
    }
    __syncthreads();
    if ((wid & 1) == 1 && lc == 0) {
        float* ps = psum + ((size_t)(b * NMT + mt)) * NHW + n0;
        #pragma unroll
        for (int i = 0; i < 4; i++) {
            int lrow = wm + i * 16 + lr;
            ps[lrow]     = srow[lrow]     + rs0[i];
            ps[lrow + 8] = srow[lrow + 8] + rs1[i];
        }
    }
}

// ---------------------------------------------------------------------------
__global__ void invsum_kernel(const float* __restrict__ psum, float* __restrict__ inv) {
    int idx = blockIdx.x * 256 + threadIdx.x;
    if (idx >= NB * NHW) return;
    int b = idx / NHW, n = idx - b * NHW;
    const float* ps = psum + (size_t)b * NMT * NHW + n;
    float s = 0.f;
    #pragma unroll
    for (int mt = 0; mt < NMT; mt++) s += ps[(size_t)mt * NHW];
    inv[idx] = 1.f / s;
}

// ---------------------------------------------------------------------------
// Out (bf16): Y[c][n] = gamma * (sum_m V[c][m]*E[n][m]) * inv[n] + X[c][n].
// k-chunk 32 (bf16), double-buffered. grid (4 c, 18 n, NB), 128 thr.
// ---------------------------------------------------------------------------
__global__ void __launch_bounds__(128)
out_bf16(const __nv_bfloat16* __restrict__ V, const __nv_bfloat16* __restrict__ E,
         const float* __restrict__ inv, const float* __restrict__ X,
         const float* __restrict__ gamma, float* __restrict__ Y) {
    const int b  = blockIdx.z;
    const int c0 = blockIdx.x * 128;
    const int n0 = blockIdx.y * 128;
    const __nv_bfloat16* Vb = V + (size_t)b * NC * NHW;
    const __nv_bfloat16* Ab = E + (size_t)b * NHW * NHW;
    const float* Xb = X + (size_t)b * NC * NHW;
    const float* invb = inv + (size_t)b * NHW;
    float*       Yb = Y + (size_t)b * NC * NHW;

    __shared__ __nv_bfloat16 sV[2][128 * SB32];
    __shared__ __nv_bfloat16 sE[2][128 * SB32];

    const int tid = threadIdx.x;
    const int lane = tid & 31, wid = tid >> 5;
    const int wm = (wid >> 1) * 64, wn = (wid & 1) * 64;
    const int lr = lane >> 2, lc = lane & 3;

    const unsigned sVu = (unsigned)__cvta_generic_to_shared(&sV[0][0]);
    const unsigned sEu = (unsigned)__cvta_generic_to_shared(&sE[0][0]);

    float acc[4][8][4];
    #pragma unroll
    for (int i = 0; i < 4; i++)
        #pragma unroll
        for (int j = 0; j < 8; j++)
            #pragma unroll
            for (int q = 0; q < 4; q++) acc[i][j][q] = 0.f;

    const int NCH = NHW / 32;
    #define OUT_LOAD(ch, buf) {                                                       \
        int mm = (ch) * 32;                                                           \
        _Pragma("unroll")                                                             \
        for (int p = 0; p < 4; p++) {                                                 \
            CPA16(sVu + ((buf) * 128 * SB32 + tid * SB32 + p * 8) * 2,                \
                  Vb + (size_t)(c0 + tid) * NHW + mm + p * 8);                        \
            CPA16(sEu + ((buf) * 128 * SB32 + tid * SB32 + p * 8) * 2,                \
                  Ab + (size_t)(n0 + tid) * NHW + mm + p * 8);                        \
        }                                                                             \
    }

    OUT_LOAD(0, 0); CP_COMMIT();
    for (int ch = 0; ch < NCH; ch++) {
        int buf = ch & 1;
        if (ch + 1 < NCH) { OUT_LOAD(ch + 1, buf ^ 1); }
        CP_COMMIT();
        CP_WAIT1();
        __syncthreads();
        const __nv_bfloat16* Vs = sV[buf];
        const __nv_bfloat16* Es = sE[buf];
        #pragma unroll
        for (int ks = 0; ks < 2; ks++) {
            const int kb = ks * 16 + 2 * lc;
            unsigned a[4][4];
            #pragma unroll
            for (int i = 0; i < 4; i++) {
                int base = (wm + i * 16 + lr) * SB32 + kb;
                a[i][0] = *(const unsigned*)&Vs[base];
                a[i][1] = *(const unsigned*)&Vs[base + 8 * SB32];
                a[i][2] = *(const unsigned*)&Vs[base + 8];
                a[i][3] = *(const unsigned*)&Vs[base + 8 * SB32 + 8];
            }
            unsigned bb[8][2];
            #pragma unroll
            for (int j = 0; j < 8; j++) {
                int base = (wn + j * 8 + lr) * SB32 + kb;
                bb[j][0] = *(const unsigned*)&Es[base];
                bb[j][1] = *(const unsigned*)&Es[base + 8];
            }
            #pragma unroll
            for (int i = 0; i < 4; i++)
                #pragma unroll
                for (int j = 0; j < 8; j++)
                    mma_bf16(acc[i][j], a[i][0], a[i][1], a[i][2], a[i][3],
                             bb[j][0], bb[j][1]);
        }
        __syncthreads();
    }

    const float g = gamma[0];
    #pragma unroll
    for (int i = 0; i < 4; i++) {
        int r0 = c0 + wm + i * 16 + lr;
        int r1 = r0 + 8;
        #pragma unroll
        for (int j = 0; j < 8; j++) {
            int col = n0 + wn + j * 8 + lc * 2;
            float2 iv = *(const float2*)&invb[col];
            size_t i0 = (size_t)r0 * NHW + col;
            size_t i1 = (size_t)r1 * NHW + col;
            float2 x0 = *(const float2*)&Xb[i0];
            float2 x1 = *(const float2*)&Xb[i1];
            float2 v0 = { g * acc[i][j][0] * iv.x + x0.x, g * acc[i][j][1] * iv.y + x0.y };
            float2 v1 = { g * acc[i][j][2] * iv.x + x1.x, g * acc[i][j][3] * iv.y + x1.y };
            *(float2*)&Yb[i0] = v0;
            *(float2*)&Yb[i1] = v1;
        }
    }
    #undef OUT_LOAD
}

// ---------------------------------------------------------------------------
extern "C" void kernel_launch(void* const* d_in, const int* in_sizes, int n_in,
                              void* d_out, int out_size) {
    const float* X     = (const float*)d_in[0];
    const float* Wq    = (const float*)d_in[1];
    const float* bq    = (const float*)d_in[2];
    const float* Wk    = (const float*)d_in[3];
    const float* bk    = (const float*)d_in[4];
    const float* Wv    = (const float*)d_in[5];
    const float* bv    = (const float*)d_in[6];
    const float* gamma = (const float*)d_in[7];
    float* Y = (float*)d_out;

    __nv_bfloat16 *Qt, *Kt, *Vb, *Eb;
    float *PS, *IV;
    cudaGetSymbolAddress((void**)&Qt, g_Qt);
    cudaGetSymbolAddress((void**)&Kt, g_Kt);
    cudaGetSymbolAddress((void**)&Vb, g_Vb);
    cudaGetSymbolAddress((void**)&Eb, g_Eb);
    cudaGetSymbolAddress((void**)&PS, g_psum);
    cudaGetSymbolAddress((void**)&IV, g_inv);

    proj_tf32<true><<<dim3(NHW / 128, 1, NB), 128>>>(X, Wq, bq, Wk, bk, 64,
                                                     nullptr, Qt, Kt);
    proj_tf32<false><<<dim3(NHW / 128, NC / 128, NB), 128>>>(X, Wv, bv, Wv, bv, NC,
                                                             Vb, nullptr, nullptr);
    scores_bf16<<<dim3(NMT, NMT, NB), 128>>>(Qt, Kt, Eb, PS);
    invsum_kernel<<<(NB * NHW + 255) / 256, 256>>>(PS, IV);
    out_bf16<<<dim3(NC / 128, NHW / 128, NB), 128>>>(Vb, Eb, IV, X, gamma, Y);
}

// round 8
// speedup vs baseline: 5.3676x; 1.1333x over previous
#include <cuda_runtime.h>
#include <cuda_bf16.h>
#include <cstdint>

// DANet spatial attention — all-bf16 mma.sync(m16n8k16) GEMMs with ldmatrix.
// B=16, C=512, HW=2304, d=64. Softmax-free: scores emit exp(S) bf16 + row sums.

#define NB 16
#define NC 512
#define NHW 2304
#define ND 64
#define NMT 18

__device__ __nv_bfloat16 g_Xt [(size_t)NB * NHW * NC];   // [b][n][c] bf16
__device__ __nv_bfloat16 g_Wqk[(size_t)128 * NC];        // rows 0..63 Wq, 64..127 Wk
__device__ __nv_bfloat16 g_Wv [(size_t)NC * NC];
__device__ __nv_bfloat16 g_Qt [(size_t)NB * NHW * ND];   // [b][n][d]
__device__ __nv_bfloat16 g_Kt [(size_t)NB * NHW * ND];   // [b][m][d]
__device__ __nv_bfloat16 g_Vb [(size_t)NB * NC * NHW];   // [b][c][m]
__device__ __nv_bfloat16 g_Eb [(size_t)NB * NHW * NHW];  // [b][n][m] = exp(S)
__device__ float g_psum[(size_t)NB * NMT * NHW];
__device__ float g_inv [(size_t)NB * NHW];

// ---------------------------------------------------------------------------
__device__ __forceinline__ void mma_bf16(float c[4],
                                         unsigned a0, unsigned a1, unsigned a2, unsigned a3,
                                         unsigned b0, unsigned b1) {
    asm volatile(
        "mma.sync.aligned.m16n8k16.row.col.f32.bf16.bf16.f32 "
        "{%0,%1,%2,%3}, {%4,%5,%6,%7}, {%8,%9}, {%0,%1,%2,%3};"
        : "+f"(c[0]), "+f"(c[1]), "+f"(c[2]), "+f"(c[3])
        : "r"(a0), "r"(a1), "r"(a2), "r"(a3), "r"(b0), "r"(b1));
}
__device__ __forceinline__ void ldsm_x4(unsigned r[4], uint32_t addr) {
    asm volatile("ldmatrix.sync.aligned.m8n8.x4.shared.b16 {%0,%1,%2,%3}, [%4];"
        : "=r"(r[0]), "=r"(r[1]), "=r"(r[2]), "=r"(r[3]) : "r"(addr));
}
#define CPA16(dst, src) asm volatile("cp.async.ca.shared.global [%0], [%1], 16;\n" :: "r"(dst), "l"(src))
#define CP_COMMIT()     asm volatile("cp.async.commit_group;\n")
#define CP_WAIT1()      asm volatile("cp.async.wait_group 1;\n")
#define CP_WAIT0()      asm volatile("cp.async.wait_group 0;\n")

#define SB32 40   // bf16 stride for [row][32k] tiles (80B, 16B-aligned, LDSM conflict-free)
#define SB64 72   // bf16 stride for [row][64k] tiles (144B)

// ---------------------------------------------------------------------------
// X [b][c][n] fp32 -> Xt [b][n][c] bf16 (32x32 smem transpose)
// ---------------------------------------------------------------------------
__global__ void __launch_bounds__(256)
convert_x(const float* __restrict__ X, __nv_bfloat16* __restrict__ Xt) {
    __shared__ float t[32][33];
    const int b  = blockIdx.z;
    const int n0 = blockIdx.x * 32;
    const int c0 = blockIdx.y * 32;
    const int tx = threadIdx.x & 31, ty = threadIdx.x >> 5;   // 32 x 8
    const float* Xb = X + (size_t)b * NC * NHW;
    __nv_bfloat16* Tb = Xt + (size_t)b * NHW * NC;
    #pragma unroll
    for (int k = 0; k < 4; k++)
        t[ty + k * 8][tx] = Xb[(size_t)(c0 + ty + k * 8) * NHW + n0 + tx];
    __syncthreads();
    #pragma unroll
    for (int k = 0; k < 4; k++)
        Tb[(size_t)(n0 + ty + k * 8) * NC + c0 + tx] = __float2bfloat16(t[tx][ty + k * 8]);
}

// ---------------------------------------------------------------------------
// W's fp32 -> bf16 (Wq+Wk stacked into g_Wqk, Wv into g_Wv)
// ---------------------------------------------------------------------------
__global__ void __launch_bounds__(256)
convert_w(const float* __restrict__ Wq, const float* __restrict__ Wk,
          const float* __restrict__ Wv,
          __nv_bfloat16* __restrict__ Wqk, __nv_bfloat16* __restrict__ Wvb) {
    int idx = blockIdx.x * 256 + threadIdx.x;
    const int NQK = 128 * NC;
    if (idx < NQK) {
        int row = idx >> 9, col = idx & 511;
        float v = (row < 64) ? Wq[row * NC + col] : Wk[(row - 64) * NC + col];
        Wqk[idx] = __float2bfloat16(v);
    }
    int j = idx - NQK;
    if (j >= 0 && j < NC * NC)
        Wvb[j] = __float2bfloat16(Wv[j]);
}

// ---------------------------------------------------------------------------
// bf16 projection: C[o][n] = sum_c W[o][c] * Xt[n][c] + bias[o]
// A = W rows (RK), B = Xt rows (RK). 128x128 tile, k-chunk 32, ldmatrix.
// QKT=true -> transposed stores to Qt/Kt; else V [c][m] bf16x2.
// ---------------------------------------------------------------------------
template<bool QKT>
__global__ void __launch_bounds__(128)
proj_bf16(const __nv_bfloat16* __restrict__ Xt, const __nv_bfloat16* __restrict__ W,
          const float* __restrict__ B1, const float* __restrict__ B2, int split,
          __nv_bfloat16* __restrict__ Pv,
          __nv_bfloat16* __restrict__ Qt, __nv_bfloat16* __restrict__ Kt) {
    const int b  = blockIdx.z;
    const int n0 = blockIdx.x * 128;
    const int o0 = blockIdx.y * 128;
    const __nv_bfloat16* Xb = Xt + (size_t)b * NHW * NC;

    __shared__ __align__(16) __nv_bfloat16 sW[2][128 * SB32];
    __shared__ __align__(16) __nv_bfloat16 sX[2][128 * SB32];

    const int tid = threadIdx.x;
    const int lane = tid & 31, wid = tid >> 5;
    const int wm = (wid >> 1) * 64, wn = (wid & 1) * 64;
    const int lr = lane >> 2, lc = lane & 3;
    const int lt = lane >> 3, l8 = lane & 7;
    const int aro = ((lt & 1) << 3) + l8, ako = (lt >> 1) << 3;
    const int bro = ((lt >> 1) << 3) + l8, bko = (lt & 1) << 3;

    const unsigned sWu = (unsigned)__cvta_generic_to_shared(&sW[0][0]);
    const unsigned sXu = (unsigned)__cvta_generic_to_shared(&sX[0][0]);

    float acc[4][8][4];
    #pragma unroll
    for (int i = 0; i < 4; i++)
        #pragma unroll
        for (int j = 0; j < 8; j++)
            #pragma unroll
            for (int q = 0; q < 4; q++) acc[i][j][q] = 0.f;

    const int NCH = NC / 32;   // 16
    #define PLOAD(ch, buf) {                                                          \
        int mm = (ch) * 32;                                                           \
        _Pragma("unroll")                                                             \
        for (int p = 0; p < 4; p++) {                                                 \
            CPA16(sWu + ((buf) * 128 * SB32 + tid * SB32 + p * 8) * 2,                \
                  W  + (size_t)(o0 + tid) * NC + mm + p * 8);                         \
            CPA16(sXu + ((buf) * 128 * SB32 + tid * SB32 + p * 8) * 2,                \
                  Xb + (size_t)(n0 + tid) * NC + mm + p * 8);                         \
        }                                                                             \
    }

    PLOAD(0, 0); CP_COMMIT();
    #pragma unroll 1
    for (int ch = 0; ch < NCH; ch++) {
        int buf = ch & 1;
        if (ch + 1 < NCH) { PLOAD(ch + 1, buf ^ 1); CP_COMMIT(); CP_WAIT1(); }
        else              { CP_WAIT0(); }
        __syncthreads();
        unsigned aBase = sWu + (unsigned)(buf * 128 * SB32) * 2;
        unsigned bBase = sXu + (unsigned)(buf * 128 * SB32) * 2;
        #pragma unroll
        for (int ks = 0; ks < 2; ks++) {
            const int kb = ks * 16;
            unsigned a[4][4], rb[4][4];
            #pragma unroll
            for (int i = 0; i < 4; i++)
                ldsm_x4(a[i], aBase + ((wm + i * 16 + aro) * SB32 + kb + ako) * 2);
            #pragma unroll
            for (int j = 0; j < 4; j++)
                ldsm_x4(rb[j], bBase + ((wn + j * 16 + bro) * SB32 + kb + bko) * 2);
            #pragma unroll
            for (int i = 0; i < 4; i++)
                #pragma unroll
                for (int jj = 0; jj < 8; jj++)
                    mma_bf16(acc[i][jj], a[i][0], a[i][1], a[i][2], a[i][3],
                             rb[jj >> 1][(jj & 1) * 2], rb[jj >> 1][(jj & 1) * 2 + 1]);
        }
        __syncthreads();
    }

    if (QKT) {
        __nv_bfloat16* Qb = Qt + (size_t)b * NHW * ND;
        __nv_bfloat16* Kb = Kt + (size_t)b * NHW * ND;
        #pragma unroll
        for (int i = 0; i < 4; i++) {
            int r0 = o0 + wm + i * 16 + lr;
            int r1 = r0 + 8;
            float bo0 = (r0 < split ? B1[r0] : B2[r0 - split]);
            float bo1 = (r1 < split ? B1[r1] : B2[r1 - split]);
            __nv_bfloat16* P0 = (r0 < split ? Qb : Kb);
            __nv_bfloat16* P1 = (r1 < split ? Qb : Kb);
            int rr0 = (r0 < split ? r0 : r0 - split);
            int rr1 = (r1 < split ? r1 : r1 - split);
            #pragma unroll
            for (int j = 0; j < 8; j++) {
                int col = n0 + wn + j * 8 + lc * 2;
                P0[(size_t)col * ND + rr0]       = __float2bfloat16(acc[i][j][0] + bo0);
                P0[(size_t)(col + 1) * ND + rr0] = __float2bfloat16(acc[i][j][1] + bo0);
                P1[(size_t)col * ND + rr1]       = __float2bfloat16(acc[i][j][2] + bo1);
                P1[(size_t)(col + 1) * ND + rr1] = __float2bfloat16(acc[i][j][3] + bo1);
            }
        }
    } else {
        __nv_bfloat16* Pb = Pv + (size_t)b * NC * NHW;
        #pragma unroll
        for (int i = 0; i < 4; i++) {
            int r0 = o0 + wm + i * 16 + lr;
            int r1 = r0 + 8;
            float bo0 = B1[r0];
            float bo1 = B1[r1];
            #pragma unroll
            for (int j = 0; j < 8; j++) {
                int col = n0 + wn + j * 8 + lc * 2;
                __nv_bfloat162 v0 = __floats2bfloat162_rn(acc[i][j][0] + bo0, acc[i][j][1] + bo0);
                __nv_bfloat162 v1 = __floats2bfloat162_rn(acc[i][j][2] + bo1, acc[i][j][3] + bo1);
                *(__nv_bfloat162*)&Pb[(size_t)r0 * NHW + col] = v0;
                *(__nv_bfloat162*)&Pb[(size_t)r1 * NHW + col] = v1;
            }
        }
    }
    #undef PLOAD
}

// ---------------------------------------------------------------------------
// Scores+exp: E[n][m] = bf16(exp(sum_d Qt[n][d]*Kt[m][d])) + row psums.
// Single k=64 pass, ldmatrix fragments. grid (18 m, 18 n, NB), 128 thr.
// ---------------------------------------------------------------------------
__global__ void __launch_bounds__(128)
scores_bf16(const __nv_bfloat16* __restrict__ Qt, const __nv_bfloat16* __restrict__ Kt,
            __nv_bfloat16* __restrict__ E, float* __restrict__ psum) {
    const int b  = blockIdx.z;
    const int mt = blockIdx.x;
    const int m0 = mt * 128;
    const int n0 = blockIdx.y * 128;
    const __nv_bfloat16* Qb = Qt + (size_t)b * NHW * ND;
    const __nv_bfloat16* Kb = Kt + (size_t)b * NHW * ND;
    __nv_bfloat16*       Eb = E + (size_t)b * NHW * NHW;

    __shared__ __align__(16) __nv_bfloat16 sQ[128 * SB64];
    __shared__ __align__(16) __nv_bfloat16 sK[128 * SB64];
    __shared__ float srow[128];

    const int tid = threadIdx.x;
    const int lane = tid & 31, wid = tid >> 5;
    const int wm = (wid >> 1) * 64, wn = (wid & 1) * 64;
    const int lr = lane >> 2, lc = lane & 3;
    const int lt = lane >> 3, l8 = lane & 7;
    const int aro = ((lt & 1) << 3) + l8, ako = (lt >> 1) << 3;
    const int bro = ((lt >> 1) << 3) + l8, bko = (lt & 1) << 3;

    const unsigned sQu = (unsigned)__cvta_generic_to_shared(&sQ[0]);
    const unsigned sKu = (unsigned)__cvta_generic_to_shared(&sK[0]);

    #pragma unroll
    for (int p = 0; p < 8; p++) {
        int idx = tid + p * 128;
        int row = idx >> 3, c = idx & 7;
        CPA16(sQu + (row * SB64 + c * 8) * 2, Qb + (size_t)(n0 + row) * ND + c * 8);
        CPA16(sKu + (row * SB64 + c * 8) * 2, Kb + (size_t)(m0 + row) * ND + c * 8);
    }
    CP_COMMIT();

    float acc[4][8][4];
    #pragma unroll
    for (int i = 0; i < 4; i++)
        #pragma unroll
        for (int j = 0; j < 8; j++)
            #pragma unroll
            for (int q = 0; q < 4; q++) acc[i][j][q] = 0.f;

    CP_WAIT0();
    __syncthreads();

    #pragma unroll
    for (int t4 = 0; t4 < 4; t4++) {
        const int kb = t4 * 16;
        unsigned a[4][4], rb[4][4];
        #pragma unroll
        for (int i = 0; i < 4; i++)
            ldsm_x4(a[i], sQu + ((wm + i * 16 + aro) * SB64 + kb + ako) * 2);
        #pragma unroll
        for (int j = 0; j < 4; j++)
            ldsm_x4(rb[j], sKu + ((wn + j * 16 + bro) * SB64 + kb + bko) * 2);
        #pragma unroll
        for (int i = 0; i < 4; i++)
            #pragma unroll
            for (int jj = 0; jj < 8; jj++)
                mma_bf16(acc[i][jj], a[i][0], a[i][1], a[i][2], a[i][3],
                         rb[jj >> 1][(jj & 1) * 2], rb[jj >> 1][(jj & 1) * 2 + 1]);
    }

    // epilogue: exp -> bf16 store + per-row partial sums of rounded values
    float rs0[4], rs1[4];
    #pragma unroll
    for (int i = 0; i < 4; i++) {
        int r0 = n0 + wm + i * 16 + lr;
        int r1 = r0 + 8;
        float s0 = 0.f, s1 = 0.f;
        #pragma unroll
        for (int j = 0; j < 8; j++) {
            int col = m0 + wn + j * 8 + lc * 2;
            __nv_bfloat162 h0 = __floats2bfloat162_rn(__expf(acc[i][j][0]), __expf(acc[i][j][1]));
            __nv_bfloat162 h1 = __floats2bfloat162_rn(__expf(acc[i][j][2]), __expf(acc[i][j][3]));
            *(__nv_bfloat162*)&Eb[(size_t)r0 * NHW + col] = h0;
            *(__nv_bfloat162*)&Eb[(size_t)r1 * NHW + col] = h1;
            float2 f0 = __bfloat1622float2(h0);
            float2 f1 = __bfloat1622float2(h1);
            s0 += f0.x + f0.y;
            s1 += f1.x + f1.y;
        }
        s0 += __shfl_xor_sync(0xffffffffu, s0, 1);
        s0 += __shfl_xor_sync(0xffffffffu, s0, 2);
        s1 += __shfl_xor_sync(0xffffffffu, s1, 1);
        s1 += __shfl_xor_sync(0xffffffffu, s1, 2);
        rs0[i] = s0; rs1[i] = s1;
        if ((wid & 1) == 0 && lc == 0) {
            srow[wm + i * 16 + lr]     = s0;
            srow[wm + i * 16 + lr + 8] = s1;
        }
    }
    __syncthreads();
    if ((wid & 1) == 1 && lc == 0) {
        float* ps = psum + ((size_t)(b * NMT + mt)) * NHW + n0;
        #pragma unroll
        for (int i = 0; i < 4; i++) {
            int lrow = wm + i * 16 + lr;
            ps[lrow]     = srow[lrow]     + rs0[i];
            ps[lrow + 8] = srow[lrow + 8] + rs1[i];
        }
    }
}

// ---------------------------------------------------------------------------
__global__ void invsum_kernel(const float* __restrict__ psum, float* __restrict__ inv) {
    int idx = blockIdx.x * 256 + threadIdx.x;
    if (idx >= NB * NHW) return;
    int b = idx / NHW, n = idx - b * NHW;
    const float* ps = psum + (size_t)b * NMT * NHW + n;
    float s = 0.f;
    #pragma unroll
    for (int mt = 0; mt < NMT; mt++) s += ps[(size_t)mt * NHW];
    inv[idx] = 1.f / s;
}

// ---------------------------------------------------------------------------
// Out: Y[c][n] = gamma * (sum_m V[c][m]*E[n][m]) * inv[n] + X[c][n].
// k-chunk 32, double-buffered, ldmatrix. grid (4 c, 18 n, NB), 128 thr.
// ---------------------------------------------------------------------------
__global__ void __launch_bounds__(128)
out_bf16(const __nv_bfloat16* __restrict__ V, const __nv_bfloat16* __restrict__ E,
         const float* __restrict__ inv, const float* __restrict__ X,
         const float* __restrict__ gamma, float* __restrict__ Y) {
    const int b  = blockIdx.z;
    const int c0 = blockIdx.x * 128;
    const int n0 = blockIdx.y * 128;
    const __nv_bfloat16* Vb = V + (size_t)b * NC * NHW;
    const __nv_bfloat16* Ab = E + (size_t)b * NHW * NHW;
    const float* Xb = X + (size_t)b * NC * NHW;
    const float* invb = inv + (size_t)b * NHW;
    float*       Yb = Y + (size_t)b * NC * NHW;

    __shared__ __align__(16) __nv_bfloat16 sV[2][128 * SB32];
    __shared__ __align__(16) __nv_bfloat16 sE[2][128 * SB32];

    const int tid = threadIdx.x;
    const int lane = tid & 31, wid = tid >> 5;
    const int wm = (wid >> 1) * 64, wn = (wid & 1) * 64;
    const int lr = lane >> 2, lc = lane & 3;
    const int lt = lane >> 3, l8 = lane & 7;
    const int aro = ((lt & 1) << 3) + l8, ako = (lt >> 1) << 3;
    const int bro = ((lt >> 1) << 3) + l8, bko = (lt & 1) << 3;

    const unsigned sVu = (unsigned)__cvta_generic_to_shared(&sV[0][0]);
    const unsigned sEu = (unsigned)__cvta_generic_to_shared(&sE[0][0]);

    float acc[4][8][4];
    #pragma unroll
    for (int i = 0; i < 4; i++)
        #pragma unroll
        for (int j = 0; j < 8; j++)
            #pragma unroll
            for (int q = 0; q < 4; q++) acc[i][j][q] = 0.f;

    const int NCH = NHW / 32;   // 72
    #define OLOAD(ch, buf) {                                                          \
        int mm = (ch) * 32;                                                           \
        _Pragma("unroll")                                                             \
        for (int p = 0; p < 4; p++) {                                                 \
            CPA16(sVu + ((buf) * 128 * SB32 + tid * SB32 + p * 8) * 2,                \
                  Vb + (size_t)(c0 + tid) * NHW + mm + p * 8);                        \
            CPA16(sEu + ((buf) * 128 * SB32 + tid * SB32 + p * 8) * 2,                \
                  Ab + (size_t)(n0 + tid) * NHW + mm + p * 8);                        \
        }                                                                             \
    }

    OLOAD(0, 0); CP_COMMIT();
    #pragma unroll 1
    for (int ch = 0; ch < NCH; ch++) {
        int buf = ch & 1;
        if (ch + 1 < NCH) { OLOAD(ch + 1, buf ^ 1); CP_COMMIT(); CP_WAIT1(); }
        else              { CP_WAIT0(); }
        __syncthreads();
        unsigned aBase = sVu + (unsigned)(buf * 128 * SB32) * 2;
        unsigned bBase = sEu + (unsigned)(buf * 128 * SB32) * 2;
        #pragma unroll
        for (int ks = 0; ks < 2; ks++) {
            const int kb = ks * 16;
            unsigned a[4][4], rb[4][4];
            #pragma unroll
            for (int i = 0; i < 4; i++)
                ldsm_x4(a[i], aBase + ((wm + i * 16 + aro) * SB32 + kb + ako) * 2);
            #pragma unroll
            for (int j = 0; j < 4; j++)
                ldsm_x4(rb[j], bBase + ((wn + j * 16 + bro) * SB32 + kb + bko) * 2);
            #pragma unroll
            for (int i = 0; i < 4; i++)
                #pragma unroll
                for (int jj = 0; jj < 8; jj++)
                    mma_bf16(acc[i][jj], a[i][0], a[i][1], a[i][2], a[i][3],
                             rb[jj >> 1][(jj & 1) * 2], rb[jj >> 1][(jj & 1) * 2 + 1]);
        }
        __syncthreads();
    }

    const float g = gamma[0];
    #pragma unroll
    for (int i = 0; i < 4; i++) {
        int r0 = c0 + wm + i * 16 + lr;
        int r1 = r0 + 8;
        #pragma unroll
        for (int j = 0; j < 8; j++) {
            int col = n0 + wn + j * 8 + lc * 2;
            float2 iv = *(const float2*)&invb[col];
            size_t i0 = (size_t)r0 * NHW + col;
            size_t i1 = (size_t)r1 * NHW + col;
            float2 x0 = *(const float2*)&Xb[i0];
            float2 x1 = *(const float2*)&Xb[i1];
            float2 v0 = { g * acc[i][j][0] * iv.x + x0.x, g * acc[i][j][1] * iv.y + x0.y };
            float2 v1 = { g * acc[i][j][2] * iv.x + x1.x, g * acc[i][j][3] * iv.y + x1.y };
            *(float2*)&Yb[i0] = v0;
            *(float2*)&Yb[i1] = v1;
        }
    }
    #undef OLOAD
}

// ---------------------------------------------------------------------------
extern "C" void kernel_launch(void* const* d_in, const int* in_sizes, int n_in,
                              void* d_out, int out_size) {
    const float* X     = (const float*)d_in[0];
    const float* Wq    = (const float*)d_in[1];
    const float* bq    = (const float*)d_in[2];
    const float* Wk    = (const float*)d_in[3];
    const float* bk    = (const float*)d_in[4];
    const float* Wv    = (const float*)d_in[5];
    const float* bv    = (const float*)d_in[6];
    const float* gamma = (const float*)d_in[7];
    float* Y = (float*)d_out;

    __nv_bfloat16 *Xt, *Wqk, *Wvb, *Qt, *Kt, *Vb, *Eb;
    float *PS, *IV;
    cudaGetSymbolAddress((void**)&Xt,  g_Xt);
    cudaGetSymbolAddress((void**)&Wqk, g_Wqk);
    cudaGetSymbolAddress((void**)&Wvb, g_Wv);
    cudaGetSymbolAddress((void**)&Qt,  g_Qt);
    cudaGetSymbolAddress((void**)&Kt,  g_Kt);
    cudaGetSymbolAddress((void**)&Vb,  g_Vb);
    cudaGetSymbolAddress((void**)&Eb,  g_Eb);
    cudaGetSymbolAddress((void**)&PS,  g_psum);
    cudaGetSymbolAddress((void**)&IV,  g_inv);

    convert_x<<<dim3(NHW / 32, NC / 32, NB), 256>>>(X, Xt);
    convert_w<<<(128 * NC + NC * NC + 255) / 256, 256>>>(Wq, Wk, Wv, Wqk, Wvb);
    proj_bf16<true><<<dim3(NHW / 128, 1, NB), 128>>>(Xt, Wqk, bq, bk, 64,
                                                     nullptr, Qt, Kt);
    proj_bf16<false><<<dim3(NHW / 128, NC / 128, NB), 128>>>(Xt, Wvb, bv, bv, NC,
                                                             Vb, nullptr, nullptr);
    scores_bf16<<<dim3(NMT, NMT, NB), 128>>>(Qt, Kt, Eb, PS);
    invsum_kernel<<<(NB * NHW + 255) / 256, 256>>>(PS, IV);
    out_bf16<<<dim3(NC / 128, NHW / 128, NB), 128>>>(Vb, Eb, IV, X, gamma, Y);
}

// round 9
// speedup vs baseline: 6.6420x; 1.2374x over previous
#include <cuda_runtime.h>
#include <cuda_bf16.h>
#include <cstdint>

// DANet spatial attention — all-bf16 mma.sync(m16n8k16), 8-warp CTAs,
// 3-stage cp.async pipelines. B=16, C=512, HW=2304, d=64. Softmax-free.

#define NB 16
#define NC 512
#define NHW 2304
#define ND 64
#define NMT 18

__device__ __nv_bfloat16 g_Xt [(size_t)NB * NHW * NC];   // [b][n][c]
__device__ __nv_bfloat16 g_Wqk[(size_t)128 * NC];
__device__ __nv_bfloat16 g_Wv [(size_t)NC * NC];
__device__ __nv_bfloat16 g_Qt [(size_t)NB * NHW * ND];
__device__ __nv_bfloat16 g_Kt [(size_t)NB * NHW * ND];
__device__ __nv_bfloat16 g_Vb [(size_t)NB * NC * NHW];
__device__ __nv_bfloat16 g_Eb [(size_t)NB * NHW * NHW];
__device__ float g_psum[(size_t)NB * NMT * NHW];
__device__ float g_inv [(size_t)NB * NHW];

// ---------------------------------------------------------------------------
__device__ __forceinline__ void mma_bf16(float c[4],
                                         unsigned a0, unsigned a1, unsigned a2, unsigned a3,
                                         unsigned b0, unsigned b1) {
    asm volatile(
        "mma.sync.aligned.m16n8k16.row.col.f32.bf16.bf16.f32 "
        "{%0,%1,%2,%3}, {%4,%5,%6,%7}, {%8,%9}, {%0,%1,%2,%3};"
        : "+f"(c[0]), "+f"(c[1]), "+f"(c[2]), "+f"(c[3])
        : "r"(a0), "r"(a1), "r"(a2), "r"(a3), "r"(b0), "r"(b1));
}
__device__ __forceinline__ void ldsm_x4(unsigned r[4], uint32_t addr) {
    asm volatile("ldmatrix.sync.aligned.m8n8.x4.shared.b16 {%0,%1,%2,%3}, [%4];"
        : "=r"(r[0]), "=r"(r[1]), "=r"(r[2]), "=r"(r[3]) : "r"(addr));
}
#define CPA16(dst, src) asm volatile("cp.async.ca.shared.global [%0], [%1], 16;\n" :: "r"(dst), "l"(src))
#define CP_COMMIT()     asm volatile("cp.async.commit_group;\n")
#define CP_WAIT2()      asm volatile("cp.async.wait_group 2;\n")
#define CP_WAIT1()      asm volatile("cp.async.wait_group 1;\n")
#define CP_WAIT0()      asm volatile("cp.async.wait_group 0;\n")

#define SB32 40   // bf16 stride, [row][32k] tile
#define SB64 72   // bf16 stride, [row][64k] tile
#define TILE32 (128 * SB32)          // elems per 128x32 tile
#define STG_BYTES (TILE32 * 2)       // 10240 B

// ---------------------------------------------------------------------------
__global__ void __launch_bounds__(256)
convert_x(const float* __restrict__ X, __nv_bfloat16* __restrict__ Xt) {
    __shared__ float t[32][33];
    const int b  = blockIdx.z;
    const int n0 = blockIdx.x * 32;
    const int c0 = blockIdx.y * 32;
    const int tx = threadIdx.x & 31, ty = threadIdx.x >> 5;
    const float* Xb = X + (size_t)b * NC * NHW;
    __nv_bfloat16* Tb = Xt + (size_t)b * NHW * NC;
    #pragma unroll
    for (int k = 0; k < 4; k++)
        t[ty + k * 8][tx] = Xb[(size_t)(c0 + ty + k * 8) * NHW + n0 + tx];
    __syncthreads();
    #pragma unroll
    for (int k = 0; k < 4; k++)
        Tb[(size_t)(n0 + ty + k * 8) * NC + c0 + tx] = __float2bfloat16(t[tx][ty + k * 8]);
}

__global__ void __launch_bounds__(256)
convert_w(const float* __restrict__ Wq, const float* __restrict__ Wk,
          const float* __restrict__ Wv,
          __nv_bfloat16* __restrict__ Wqk, __nv_bfloat16* __restrict__ Wvb) {
    int idx = blockIdx.x * 256 + threadIdx.x;
    const int NQK = 128 * NC;
    if (idx < NQK) {
        int row = idx >> 9, col = idx & 511;
        float v = (row < 64) ? Wq[row * NC + col] : Wk[(row - 64) * NC + col];
        Wqk[idx] = __float2bfloat16(v);
    }
    int j = idx - NQK;
    if (j >= 0 && j < NC * NC)
        Wvb[j] = __float2bfloat16(Wv[j]);
}

// ---------------------------------------------------------------------------
// bf16 projection, 256 thr, 8 warps (2x4), warp tile 64x32, 3-stage pipeline.
// dyn smem: sW[3 stages] then sX[3 stages], each stage 128xSB32.
// ---------------------------------------------------------------------------
template<bool QKT>
__global__ void __launch_bounds__(256, 2)
proj_bf16(const __nv_bfloat16* __restrict__ Xt, const __nv_bfloat16* __restrict__ W,
          const float* __restrict__ B1, const float* __restrict__ B2, int split,
          __nv_bfloat16* __restrict__ Pv,
          __nv_bfloat16* __restrict__ Qt, __nv_bfloat16* __restrict__ Kt) {
    extern __shared__ __align__(16) __nv_bfloat16 dsm[];
    __nv_bfloat16* sW = dsm;
    __nv_bfloat16* sX = dsm + 3 * TILE32;

    const int b  = blockIdx.z;
    const int n0 = blockIdx.x * 128;
    const int o0 = blockIdx.y * 128;
    const __nv_bfloat16* Xb = Xt + (size_t)b * NHW * NC;

    const int tid = threadIdx.x;
    const int lane = tid & 31, wid = tid >> 5;
    const int wm = (wid >> 2) * 64, wn = (wid & 3) * 32;
    const int lr = lane >> 2, lc = lane & 3;
    const int lt = lane >> 3, l8 = lane & 7;
    const int aro = ((lt & 1) << 3) + l8, ako = (lt >> 1) << 3;
    const int bro = ((lt >> 1) << 3) + l8, bko = (lt & 1) << 3;

    const unsigned sWu = (unsigned)__cvta_generic_to_shared(sW);
    const unsigned sXu = (unsigned)__cvta_generic_to_shared(sX);

    const int lrow = tid >> 1, lc8 = (tid & 1) * 2;   // 2x16B per thread per tile

    float acc[4][4][4];
    #pragma unroll
    for (int i = 0; i < 4; i++)
        #pragma unroll
        for (int j = 0; j < 4; j++)
            #pragma unroll
            for (int q = 0; q < 4; q++) acc[i][j][q] = 0.f;

    const int NCH = NC / 32;   // 16
    #define PLOAD(ch, stg) {                                                          \
        int mm = (ch) * 32;                                                           \
        _Pragma("unroll")                                                             \
        for (int p = 0; p < 2; p++) {                                                 \
            CPA16(sWu + ((stg) * TILE32 + lrow * SB32 + (lc8 + p) * 8) * 2,           \
                  W  + (size_t)(o0 + lrow) * NC + mm + (lc8 + p) * 8);                \
            CPA16(sXu + ((stg) * TILE32 + lrow * SB32 + (lc8 + p) * 8) * 2,           \
                  Xb + (size_t)(n0 + lrow) * NC + mm + (lc8 + p) * 8);                \
        }                                                                             \
        CP_COMMIT();                                                                  \
    }

    PLOAD(0, 0); PLOAD(1, 1);
    #pragma unroll 1
    for (int ch = 0; ch < NCH; ch++) {
        int stg = ch % 3;
        if (ch + 2 < NCH) { PLOAD(ch + 2, (ch + 2) % 3); CP_WAIT2(); }
        else if (ch + 1 < NCH) { CP_WAIT1(); }
        else { CP_WAIT0(); }
        __syncthreads();
        unsigned aB = sWu + (unsigned)(stg * TILE32) * 2;
        unsigned bB = sXu + (unsigned)(stg * TILE32) * 2;
        #pragma unroll
        for (int ks = 0; ks < 2; ks++) {
            const int kb = ks * 16;
            unsigned a[4][4], rb[2][4];
            #pragma unroll
            for (int i = 0; i < 4; i++)
                ldsm_x4(a[i], aB + ((wm + i * 16 + aro) * SB32 + kb + ako) * 2);
            #pragma unroll
            for (int j = 0; j < 2; j++)
                ldsm_x4(rb[j], bB + ((wn + j * 16 + bro) * SB32 + kb + bko) * 2);
            #pragma unroll
            for (int i = 0; i < 4; i++)
                #pragma unroll
                for (int j = 0; j < 4; j++)
                    mma_bf16(acc[i][j], a[i][0], a[i][1], a[i][2], a[i][3],
                             rb[j >> 1][(j & 1) * 2], rb[j >> 1][(j & 1) * 2 + 1]);
        }
        __syncthreads();
    }

    if (QKT) {
        __nv_bfloat16* Qb = Qt + (size_t)b * NHW * ND;
        __nv_bfloat16* Kb = Kt + (size_t)b * NHW * ND;
        #pragma unroll
        for (int i = 0; i < 4; i++) {
            int r0 = o0 + wm + i * 16 + lr;
            int r1 = r0 + 8;
            float bo0 = (r0 < split ? B1[r0] : B2[r0 - split]);
            float bo1 = (r1 < split ? B1[r1] : B2[r1 - split]);
            __nv_bfloat16* P0 = (r0 < split ? Qb : Kb);
            __nv_bfloat16* P1 = (r1 < split ? Qb : Kb);
            int rr0 = (r0 < split ? r0 : r0 - split);
            int rr1 = (r1 < split ? r1 : r1 - split);
            #pragma unroll
            for (int j = 0; j < 4; j++) {
                int col = n0 + wn + j * 8 + lc * 2;
                P0[(size_t)col * ND + rr0]       = __float2bfloat16(acc[i][j][0] + bo0);
                P0[(size_t)(col + 1) * ND + rr0] = __float2bfloat16(acc[i][j][1] + bo0);
                P1[(size_t)col * ND + rr1]       = __float2bfloat16(acc[i][j][2] + bo1);
                P1[(size_t)(col + 1) * ND + rr1] = __float2bfloat16(acc[i][j][3] + bo1);
            }
        }
    } else {
        __nv_bfloat16* Pb = Pv + (size_t)b * NC * NHW;
        #pragma unroll
        for (int i = 0; i < 4; i++) {
            int r0 = o0 + wm + i * 16 + lr;
            int r1 = r0 + 8;
            float bo0 = B1[r0];
            float bo1 = B1[r1];
            #pragma unroll
            for (int j = 0; j < 4; j++) {
                int col = n0 + wn + j * 8 + lc * 2;
                __nv_bfloat162 v0 = __floats2bfloat162_rn(acc[i][j][0] + bo0, acc[i][j][1] + bo0);
                __nv_bfloat162 v1 = __floats2bfloat162_rn(acc[i][j][2] + bo1, acc[i][j][3] + bo1);
                *(__nv_bfloat162*)&Pb[(size_t)r0 * NHW + col] = v0;
                *(__nv_bfloat162*)&Pb[(size_t)r1 * NHW + col] = v1;
            }
        }
    }
    #undef PLOAD
}

// ---------------------------------------------------------------------------
// Scores+exp, 256 thr, 8 warps (2x4), warp tile 64x32, single k=64 pass.
// ---------------------------------------------------------------------------
__global__ void __launch_bounds__(256, 2)
scores_bf16(const __nv_bfloat16* __restrict__ Qt, const __nv_bfloat16* __restrict__ Kt,
            __nv_bfloat16* __restrict__ E, float* __restrict__ psum) {
    const int b  = blockIdx.z;
    const int mt = blockIdx.x;
    const int m0 = mt * 128;
    const int n0 = blockIdx.y * 128;
    const __nv_bfloat16* Qb = Qt + (size_t)b * NHW * ND;
    const __nv_bfloat16* Kb = Kt + (size_t)b * NHW * ND;
    __nv_bfloat16*       Eb = E + (size_t)b * NHW * NHW;

    __shared__ __align__(16) __nv_bfloat16 sQ[128 * SB64];
    __shared__ __align__(16) __nv_bfloat16 sK[128 * SB64];
    __shared__ float sred[4][128];

    const int tid = threadIdx.x;
    const int lane = tid & 31, wid = tid >> 5;
    const int wm = (wid >> 2) * 64, wn = (wid & 3) * 32;
    const int lr = lane >> 2, lc = lane & 3;
    const int lt = lane >> 3, l8 = lane & 7;
    const int aro = ((lt & 1) << 3) + l8, ako = (lt >> 1) << 3;
    const int bro = ((lt >> 1) << 3) + l8, bko = (lt & 1) << 3;

    const unsigned sQu = (unsigned)__cvta_generic_to_shared(&sQ[0]);
    const unsigned sKu = (unsigned)__cvta_generic_to_shared(&sK[0]);

    #pragma unroll
    for (int p = 0; p < 4; p++) {
        int idx = tid + p * 256;
        int row = idx >> 3, c = idx & 7;
        CPA16(sQu + (row * SB64 + c * 8) * 2, Qb + (size_t)(n0 + row) * ND + c * 8);
        CPA16(sKu + (row * SB64 + c * 8) * 2, Kb + (size_t)(m0 + row) * ND + c * 8);
    }
    CP_COMMIT();

    float acc[4][4][4];
    #pragma unroll
    for (int i = 0; i < 4; i++)
        #pragma unroll
        for (int j = 0; j < 4; j++)
            #pragma unroll
            for (int q = 0; q < 4; q++) acc[i][j][q] = 0.f;

    CP_WAIT0();
    __syncthreads();

    #pragma unroll
    for (int t4 = 0; t4 < 4; t4++) {
        const int kb = t4 * 16;
        unsigned a[4][4], rb[2][4];
        #pragma unroll
        for (int i = 0; i < 4; i++)
            ldsm_x4(a[i], sQu + ((wm + i * 16 + aro) * SB64 + kb + ako) * 2);
        #pragma unroll
        for (int j = 0; j < 2; j++)
            ldsm_x4(rb[j], sKu + ((wn + j * 16 + bro) * SB64 + kb + bko) * 2);
        #pragma unroll
        for (int i = 0; i < 4; i++)
            #pragma unroll
            for (int j = 0; j < 4; j++)
                mma_bf16(acc[i][j], a[i][0], a[i][1], a[i][2], a[i][3],
                         rb[j >> 1][(j & 1) * 2], rb[j >> 1][(j & 1) * 2 + 1]);
    }

    // epilogue: exp -> bf16 store + per-warp row partials -> 4-way combine
    const int cw = wid & 3;
    #pragma unroll
    for (int i = 0; i < 4; i++) {
        int r0 = n0 + wm + i * 16 + lr;
        int r1 = r0 + 8;
        float s0 = 0.f, s1 = 0.f;
        #pragma unroll
        for (int j = 0; j < 4; j++) {
            int col = m0 + wn + j * 8 + lc * 2;
            __nv_bfloat162 h0 = __floats2bfloat162_rn(__expf(acc[i][j][0]), __expf(acc[i][j][1]));
            __nv_bfloat162 h1 = __floats2bfloat162_rn(__expf(acc[i][j][2]), __expf(acc[i][j][3]));
            *(__nv_bfloat162*)&Eb[(size_t)r0 * NHW + col] = h0;
            *(__nv_bfloat162*)&Eb[(size_t)r1 * NHW + col] = h1;
            float2 f0 = __bfloat1622float2(h0);
            float2 f1 = __bfloat1622float2(h1);
            s0 += f0.x + f0.y;
            s1 += f1.x + f1.y;
        }
        s0 += __shfl_xor_sync(0xffffffffu, s0, 1);
        s0 += __shfl_xor_sync(0xffffffffu, s0, 2);
        s1 += __shfl_xor_sync(0xffffffffu, s1, 1);
        s1 += __shfl_xor_sync(0xffffffffu, s1, 2);
        if (lc == 0) {
            sred[cw][wm + i * 16 + lr]     = s0;
            sred[cw][wm + i * 16 + lr + 8] = s1;
        }
    }
    __syncthreads();
    if (tid < 128) {
        float s = sred[0][tid] + sred[1][tid] + sred[2][tid] + sred[3][tid];
        psum[((size_t)(b * NMT + mt)) * NHW + n0 + tid] = s;
    }
}

// ---------------------------------------------------------------------------
__global__ void invsum_kernel(const float* __restrict__ psum, float* __restrict__ inv) {
    int idx = blockIdx.x * 256 + threadIdx.x;
    if (idx >= NB * NHW) return;
    int b = idx / NHW, n = idx - b * NHW;
    const float* ps = psum + (size_t)b * NMT * NHW + n;
    float s = 0.f;
    #pragma unroll
    for (int mt = 0; mt < NMT; mt++) s += ps[(size_t)mt * NHW];
    inv[idx] = 1.f / s;
}

// ---------------------------------------------------------------------------
// Out, 256 thr, 8 warps (2x4), warp tile 64x32, 3-stage pipeline, NCH=72.
// dyn smem: sV[3] then sE[3], each stage 128xSB32.
// ---------------------------------------------------------------------------
__global__ void __launch_bounds__(256, 2)
out_bf16(const __nv_bfloat16* __restrict__ V, const __nv_bfloat16* __restrict__ E,
         const float* __restrict__ inv, const float* __restrict__ X,
         const float* __restrict__ gamma, float* __restrict__ Y) {
    extern __shared__ __align__(16) __nv_bfloat16 dsm[];
    __nv_bfloat16* sV = dsm;
    __nv_bfloat16* sE = dsm + 3 * TILE32;

    const int b  = blockIdx.z;
    const int c0 = blockIdx.x * 128;
    const int n0 = blockIdx.y * 128;
    const __nv_bfloat16* Vb = V + (size_t)b * NC * NHW;
    const __nv_bfloat16* Ab = E + (size_t)b * NHW * NHW;
    const float* Xb = X + (size_t)b * NC * NHW;
    const float* invb = inv + (size_t)b * NHW;
    float*       Yb = Y + (size_t)b * NC * NHW;

    const int tid = threadIdx.x;
    const int lane = tid & 31, wid = tid >> 5;
    const int wm = (wid >> 2) * 64, wn = (wid & 3) * 32;
    const int lr = lane >> 2, lc = lane & 3;
    const int lt = lane >> 3, l8 = lane & 7;
    const int aro = ((lt & 1) << 3) + l8, ako = (lt >> 1) << 3;
    const int bro = ((lt >> 1) << 3) + l8, bko = (lt & 1) << 3;

    const unsigned sVu = (unsigned)__cvta_generic_to_shared(sV);
    const unsigned sEu = (unsigned)__cvta_generic_to_shared(sE);

    const int lrow = tid >> 1, lc8 = (tid & 1) * 2;

    float acc[4][4][4];
    #pragma unroll
    for (int i = 0; i < 4; i++)
        #pragma unroll
        for (int j = 0; j < 4; j++)
            #pragma unroll
            for (int q = 0; q < 4; q++) acc[i][j][q] = 0.f;

    const int NCH = NHW / 32;   // 72
    #define OLOAD(ch, stg) {                                                          \
        int mm = (ch) * 32;                                                           \
        _Pragma("unroll")                                                             \
        for (int p = 0; p < 2; p++) {                                                 \
            CPA16(sVu + ((stg) * TILE32 + lrow * SB32 + (lc8 + p) * 8) * 2,           \
                  Vb + (size_t)(c0 + lrow) * NHW + mm + (lc8 + p) * 8);               \
            CPA16(sEu + ((stg) * TILE32 + lrow * SB32 + (lc8 + p) * 8) * 2,           \
                  Ab + (size_t)(n0 + lrow) * NHW + mm + (lc8 + p) * 8);               \
        }                                                                             \
        CP_COMMIT();                                                                  \
    }

    OLOAD(0, 0); OLOAD(1, 1);
    #pragma unroll 1
    for (int ch = 0; ch < NCH; ch++) {
        int stg = ch % 3;
        if (ch + 2 < NCH) { OLOAD(ch + 2, (ch + 2) % 3); CP_WAIT2(); }
        else if (ch + 1 < NCH) { CP_WAIT1(); }
        else { CP_WAIT0(); }
        __syncthreads();
        unsigned aB = sVu + (unsigned)(stg * TILE32) * 2;
        unsigned bB = sEu + (unsigned)(stg * TILE32) * 2;
        #pragma unroll
        for (int ks = 0; ks < 2; ks++) {
            const int kb = ks * 16;
            unsigned a[4][4], rb[2][4];
            #pragma unroll
            for (int i = 0; i < 4; i++)
                ldsm_x4(a[i], aB + ((wm + i * 16 + aro) * SB32 + kb + ako) * 2);
            #pragma unroll
            for (int j = 0; j < 2; j++)
                ldsm_x4(rb[j], bB + ((wn + j * 16 + bro) * SB32 + kb + bko) * 2);
            #pragma unroll
            for (int i = 0; i < 4; i++)
                #pragma unroll
                for (int j = 0; j < 4; j++)
                    mma_bf16(acc[i][j], a[i][0], a[i][1], a[i][2], a[i][3],
                             rb[j >> 1][(j & 1) * 2], rb[j >> 1][(j & 1) * 2 + 1]);
        }
        __syncthreads();
    }

    const float g = gamma[0];
    #pragma unroll
    for (int i = 0; i < 4; i++) {
        int r0 = c0 + wm + i * 16 + lr;
        int r1 = r0 + 8;
        #pragma unroll
        for (int j = 0; j < 4; j++) {
            int col = n0 + wn + j * 8 + lc * 2;
            float2 iv = *(const float2*)&invb[col];
            size_t i0 = (size_t)r0 * NHW + col;
            size_t i1 = (size_t)r1 * NHW + col;
            float2 x0 = *(const float2*)&Xb[i0];
            float2 x1 = *(const float2*)&Xb[i1];
            float2 v0 = { g * acc[i][j][0] * iv.x + x0.x, g * acc[i][j][1] * iv.y + x0.y };
            float2 v1 = { g * acc[i][j][2] * iv.x + x1.x, g * acc[i][j][3] * iv.y + x1.y };
            *(float2*)&Yb[i0] = v0;
            *(float2*)&Yb[i1] = v1;
        }
    }
    #undef OLOAD
}

// ---------------------------------------------------------------------------
extern "C" void kernel_launch(void* const* d_in, const int* in_sizes, int n_in,
                              void* d_out, int out_size) {
    const float* X     = (const float*)d_in[0];
    const float* Wq    = (const float*)d_in[1];
    const float* bq    = (const float*)d_in[2];
    const float* Wk    = (const float*)d_in[3];
    const float* bk    = (const float*)d_in[4];
    const float* Wv    = (const float*)d_in[5];
    const float* bv    = (const float*)d_in[6];
    const float* gamma = (const float*)d_in[7];
    float* Y = (float*)d_out;

    __nv_bfloat16 *Xt, *Wqk, *Wvb, *Qt, *Kt, *Vb, *Eb;
    float *PS, *IV;
    cudaGetSymbolAddress((void**)&Xt,  g_Xt);
    cudaGetSymbolAddress((void**)&Wqk, g_Wqk);
    cudaGetSymbolAddress((void**)&Wvb, g_Wv);
    cudaGetSymbolAddress((void**)&Qt,  g_Qt);
    cudaGetSymbolAddress((void**)&Kt,  g_Kt);
    cudaGetSymbolAddress((void**)&Vb,  g_Vb);
    cudaGetSymbolAddress((void**)&Eb,  g_Eb);
    cudaGetSymbolAddress((void**)&PS,  g_psum);
    cudaGetSymbolAddress((void**)&IV,  g_inv);

    const int DSM = 6 * STG_BYTES;   // 61440 B
    cudaFuncSetAttribute(proj_bf16<true>,  cudaFuncAttributeMaxDynamicSharedMemorySize, DSM);
    cudaFuncSetAttribute(proj_bf16<false>, cudaFuncAttributeMaxDynamicSharedMemorySize, DSM);
    cudaFuncSetAttribute(out_bf16,         cudaFuncAttributeMaxDynamicSharedMemorySize, DSM);

    convert_x<<<dim3(NHW / 32, NC / 32, NB), 256>>>(X, Xt);
    convert_w<<<(128 * NC + NC * NC + 255) / 256, 256>>>(Wq, Wk, Wv, Wqk, Wvb);
    proj_bf16<true><<<dim3(NHW / 128, 1, NB), 256, DSM>>>(Xt, Wqk, bq, bk, 64,
                                                          nullptr, Qt, Kt);
    proj_bf16<false><<<dim3(NHW / 128, NC / 128, NB), 256, DSM>>>(Xt, Wvb, bv, bv, NC,
                                                                  Vb, nullptr, nullptr);
    scores_bf16<<<dim3(NMT, NMT, NB), 256>>>(Qt, Kt, Eb, PS);
    invsum_kernel<<<(NB * NHW + 255) / 256, 256>>>(PS, IV);
    out_bf16<<<dim3(NC / 128, NHW / 128, NB), 256, DSM>>>(Vb, Eb, IV, X, gamma, Y);
}